// round 13
// baseline (speedup 1.0000x reference)
#include <cuda_runtime.h>
#include <cuda_fp16.h>
#include <math.h>
#include <stdint.h>

#define TT 2048
#define HH 2048
#define II 1024
#define EE 32
#define TOPK 4
#define NROUTED (TT*TOPK)
#define NPAIRS  (NROUTED + TT)

#define BM 128
#define BN 128
#define BK 64
#define NTHR 256
#define ROWB 144
#define OFF_A  0
#define OFF_B  18432            // phase B: 128 rows
#define OFF_B1 18432            // phase A: 64 rows W1
#define OFF_B3 27648            // phase A: 64 rows W3
#define BUFSZ 36864
#define SMEM_DYN (2*BUFSZ)

// ---------------- device scratch ----------------
__device__ int   g_counts[EE];
__device__ int   g_cursor[EE];
__device__ int   g_offsets[EE];
__device__ int   g_topk_idx[NROUTED];
__device__ float g_topk_w[NROUTED];
__device__ int   g_pair_token[NROUTED];
__device__ int   g_pair_pos[NROUTED];
__device__ __half g_xh[(size_t)TT*HH];
__device__ __half g_acth[(size_t)NPAIRS*II];
__device__ float g_pairout[(size_t)NPAIRS*HH];

// ---------------- helpers ----------------
__device__ __forceinline__ void cvt2h(unsigned &r, float hi_elem, float lo_elem) {
    asm("cvt.rn.f16x2.f32 %0, %1, %2;" : "=r"(r) : "f"(hi_elem), "f"(lo_elem));
}
__device__ __forceinline__ void ldsm4(unsigned &r0, unsigned &r1, unsigned &r2, unsigned &r3,
                                      unsigned addr) {
    asm volatile("ldmatrix.sync.aligned.m8n8.x4.shared.b16 {%0,%1,%2,%3}, [%4];"
                 : "=r"(r0), "=r"(r1), "=r"(r2), "=r"(r3) : "r"(addr));
}
__device__ __forceinline__ void mma16816(float* c, const unsigned* a, unsigned b0, unsigned b1) {
    asm volatile("mma.sync.aligned.m16n8k16.row.col.f32.f16.f16.f32 "
                 "{%0,%1,%2,%3}, {%4,%5,%6,%7}, {%8,%9}, {%0,%1,%2,%3};"
                 : "+f"(c[0]), "+f"(c[1]), "+f"(c[2]), "+f"(c[3])
                 : "r"(a[0]), "r"(a[1]), "r"(a[2]), "r"(a[3]), "r"(b0), "r"(b1));
}
__device__ __forceinline__ void cp16(unsigned dst, const void* src) {
    asm volatile("cp.async.cg.shared.global [%0], [%1], 16;" :: "r"(dst), "l"(src));
}

// ---------------- small kernels ----------------
__global__ void zero_kernel() {
    int i = threadIdx.x;
    if (i < EE) { g_counts[i] = 0; g_cursor[i] = 0; }
}
__global__ void offsets_kernel() {
    if (threadIdx.x == 0) {
        int s = 0;
        for (int e = 0; e < EE; ++e) { g_offsets[e] = s; s += g_counts[e]; }
    }
}
__global__ void scatter_kernel() {
    int t = blockIdx.x * blockDim.x + threadIdx.x;
    if (t >= TT) return;
    #pragma unroll
    for (int j = 0; j < TOPK; ++j) {
        int e = g_topk_idx[t*TOPK + j];
        int pos = g_offsets[e] + atomicAdd(&g_cursor[e], 1);
        g_pair_token[pos] = t;
        g_pair_pos[t*TOPK + j] = pos;
    }
}

// ---------------- gate + routing + x->fp16 (fused) ----------------
__global__ __launch_bounds__(256) void gate_kernel(
        const float* __restrict__ x, const float* __restrict__ gw,
        const float* __restrict__ bias)
{
    __shared__ float xs[4][HH];
    __shared__ float logits_s[4][EE];
    __shared__ float bias_s[EE];
    int tid = threadIdx.x;
    int t0  = blockIdx.x * 4;
    const float4* xg  = (const float4*)(x + (size_t)t0 * HH);
    float4*       xs4 = (float4*)&xs[0][0];
    #pragma unroll
    for (int i = 0; i < 8; ++i) xs4[tid + i*256] = xg[tid + i*256];
    if (tid < EE) bias_s[tid] = bias[tid];
    __syncthreads();

    // fused convx
    {
        uint2* dst = (uint2*)(g_xh + (size_t)t0 * HH);
        #pragma unroll
        for (int i = 0; i < 8; ++i) {
            float4 v = xs4[tid + i*256];
            unsigned h01, h23;
            cvt2h(h01, v.y, v.x);
            cvt2h(h23, v.w, v.z);
            dst[tid + i*256] = make_uint2(h01, h23);
        }
    }

    int warp = tid >> 5, lane = tid & 31;
    #pragma unroll
    for (int ei = 0; ei < 4; ++ei) {
        int e = warp*4 + ei;
        const float* gr = gw + (size_t)e * HH;
        float a0=0.f, a1=0.f, a2=0.f, a3=0.f;
        for (int h = lane; h < HH; h += 32) {
            float g = gr[h];
            a0 = fmaf(g, xs[0][h], a0); a1 = fmaf(g, xs[1][h], a1);
            a2 = fmaf(g, xs[2][h], a2); a3 = fmaf(g, xs[3][h], a3);
        }
        #pragma unroll
        for (int off = 16; off; off >>= 1) {
            a0 += __shfl_xor_sync(0xffffffffu, a0, off);
            a1 += __shfl_xor_sync(0xffffffffu, a1, off);
            a2 += __shfl_xor_sync(0xffffffffu, a2, off);
            a3 += __shfl_xor_sync(0xffffffffu, a3, off);
        }
        if (lane == 0) {
            logits_s[0][e] = a0; logits_s[1][e] = a1;
            logits_s[2][e] = a2; logits_s[3][e] = a3;
        }
    }
    __syncthreads();
    if (warp < 4) {
        int t = t0 + warp;
        float logit = logits_s[warp][lane];
        float s   = 1.f / (1.f + expf(-logit));
        float sfc = s + bias_s[lane];
        float m1 = sfc, m2 = -INFINITY;
        #pragma unroll
        for (int off = 4; off >= 1; off >>= 1) {
            float o1 = __shfl_xor_sync(0xffffffffu, m1, off);
            float o2 = __shfl_xor_sync(0xffffffffu, m2, off);
            float hi = fmaxf(m1, o1);
            float lo = fmaxf(fminf(m1, o1), fmaxf(m2, o2));
            m1 = hi; m2 = lo;
        }
        float gs = m1 + m2;
        float gv[4];
        gv[0] = __shfl_sync(0xffffffffu, gs, 0);
        gv[1] = __shfl_sync(0xffffffffu, gs, 8);
        gv[2] = __shfl_sync(0xffffffffu, gs, 16);
        gv[3] = __shfl_sync(0xffffffffu, gs, 24);
        int b1 = 0; float v1 = gv[0];
        #pragma unroll
        for (int gg = 1; gg < 4; ++gg) if (gv[gg] > v1) { v1 = gv[gg]; b1 = gg; }
        int b2 = -1; float v2 = -INFINITY;
        #pragma unroll
        for (int gg = 0; gg < 4; ++gg) {
            if (gg == b1) continue;
            if (gv[gg] > v2) { v2 = gv[gg]; b2 = gg; }
        }
        int mygrp = lane >> 3;
        float val = (mygrp == b1 || mygrp == b2) ? sfc : 0.0f;
        int sel_i[TOPK]; float sel_w[TOPK];
        float cur = val;
        #pragma unroll
        for (int j = 0; j < TOPK; ++j) {
            float bv = cur; int bi = lane;
            #pragma unroll
            for (int off = 16; off >= 1; off >>= 1) {
                float ov = __shfl_xor_sync(0xffffffffu, bv, off);
                int   oi = __shfl_xor_sync(0xffffffffu, bi, off);
                if (ov > bv || (ov == bv && oi < bi)) { bv = ov; bi = oi; }
            }
            sel_i[j] = bi;
            sel_w[j] = __shfl_sync(0xffffffffu, s, bi);
            if (lane == bi) cur = -INFINITY;
        }
        if (lane == 0) {
            float sum = sel_w[0] + sel_w[1] + sel_w[2] + sel_w[3];
            float scale = 2.5f / (sum + 1e-20f);
            #pragma unroll
            for (int j = 0; j < TOPK; ++j) {
                g_topk_idx[t*TOPK + j] = sel_i[j];
                g_topk_w[t*TOPK + j]   = sel_w[j] * scale;
                atomicAdd(&g_counts[sel_i[j]], 1);
            }
        }
    }
}

// ---------------- phase A: dual-matrix GEMM + fused SwiGLU -> fp16 act ----------------
// block computes 128x64 of BOTH c1=X@W1^T and c3=X@W3^T, then act = silu(c1)*c3.
// 8 warps = 2(M) x 4(N); warp tile 64x16 per matrix.
__global__ void __launch_bounds__(NTHR, 2) gemmA_kernel(
    const float* __restrict__ w1, const float* __restrict__ ws1,
    const float* __restrict__ w3, const float* __restrict__ ws3)
{
    const int g     = blockIdx.z;
    const int mtile = blockIdx.x;
    const int n0    = blockIdx.y * 64;

    int m_count, base_pos;
    if (g < EE) { m_count = g_counts[g]; base_pos = g_offsets[g]; }
    else        { m_count = TT;          base_pos = NROUTED; }
    if (mtile * BM >= m_count) return;
    const int rows = min(BM, m_count - mtile * BM);

    const size_t wsz = (size_t)II * HH;
    const float* W1 = (g < EE) ? (w1 + (size_t)g * wsz) : ws1;
    const float* W3 = (g < EE) ? (w3 + (size_t)g * wsz) : ws3;

    extern __shared__ char sm[];
    __shared__ int s_toks[BM];
    const unsigned smb = (unsigned)__cvta_generic_to_shared(sm);
    const int tid = threadIdx.x;
    if (tid < BM) {
        int r = min(tid, rows - 1);
        int pos = base_pos + mtile*BM + r;
        s_toks[tid] = (g < EE) ? g_pair_token[pos] : (mtile*BM + r);
    }
    __syncthreads();

    const int S = HH / BK;
    const int warp = tid >> 5, lane = tid & 31;
    const int wm   = (warp & 1) * 64;
    const int wn16 = (warp >> 1) * 16;
    const int l15 = lane & 15, lh = lane >> 4;

    float acc1[4][2][4], acc3[4][2][4];
    #pragma unroll
    for (int i = 0; i < 4; ++i)
        #pragma unroll
        for (int j = 0; j < 2; ++j)
            #pragma unroll
            for (int q = 0; q < 4; ++q) { acc1[i][j][q] = 0.f; acc3[i][j][q] = 0.f; }

    #define A_LOAD(dstb, k0) do {                                              \
        _Pragma("unroll")                                                      \
        for (int t = 0; t < 4; ++t) {                                          \
            int c = tid + t*NTHR;                                              \
            int row = c >> 3, ch = c & 7;                                      \
            const __half* srcp = g_xh + (size_t)s_toks[row]*HH + (k0) + ch*8;  \
            cp16((dstb) + OFF_A + row*ROWB + ch*16, srcp);                     \
        }                                                                      \
    } while(0)
    // half h: fp32 cols [h*32,h*32+32) = 8 float4/row; 64 rows x 8 = 512 per matrix
    #define AB_LDG(bv, k0, h) do {                                             \
        _Pragma("unroll")                                                      \
        for (int t = 0; t < 4; ++t) {                                          \
            int c = tid + t*NTHR;                                              \
            int idx = c & 511;                                                 \
            int row = idx >> 3, f4 = idx & 7;                                  \
            const float* Wp = (t < 2) ? W1 : W3;                               \
            (bv)[t] = *(const float4*)(Wp + (size_t)(n0+row)*HH + (k0) + (h)*32 + f4*4); \
        }                                                                      \
    } while(0)
    #define AB_STS(bv, dstg, h) do {                                           \
        _Pragma("unroll")                                                      \
        for (int t = 0; t < 4; ++t) {                                          \
            int c = tid + t*NTHR;                                              \
            int idx = c & 511;                                                 \
            int row = idx >> 3, f4 = idx & 7;                                  \
            unsigned h01, h23;                                                 \
            cvt2h(h01, (bv)[t].y, (bv)[t].x);                                  \
            cvt2h(h23, (bv)[t].w, (bv)[t].z);                                  \
            *(uint2*)((dstg) + ((t < 2) ? OFF_B1 : OFF_B3) + row*ROWB + (h)*64 + f4*8) = make_uint2(h01, h23); \
        }                                                                      \
    } while(0)
    #define A_COMPUTE(cb, kk0) do {                                            \
        _Pragma("unroll")                                                      \
        for (int kk = (kk0); kk < (kk0) + 32; kk += 16) {                      \
            unsigned b1r[4], b3r[4];                                           \
            unsigned ab1 = (cb) + OFF_B1 + (wn16 + l15)*ROWB + (kk + lh*8)*2;  \
            unsigned ab3 = (cb) + OFF_B3 + (wn16 + l15)*ROWB + (kk + lh*8)*2;  \
            ldsm4(b1r[0], b1r[1], b1r[2], b1r[3], ab1);                        \
            ldsm4(b3r[0], b3r[1], b3r[2], b3r[3], ab3);                        \
            _Pragma("unroll")                                                  \
            for (int mf = 0; mf < 4; ++mf) {                                   \
                unsigned ah[4];                                                \
                unsigned aa = (cb) + OFF_A + (wm + mf*16 + l15)*ROWB + (kk + lh*8)*2; \
                ldsm4(ah[0], ah[1], ah[2], ah[3], aa);                         \
                _Pragma("unroll")                                              \
                for (int u = 0; u < 2; ++u) {                                  \
                    mma16816(acc1[mf][u], ah, b1r[u], b1r[2 + u]);             \
                    mma16816(acc3[mf][u], ah, b3r[u], b3r[2 + u]);             \
                }                                                              \
            }                                                                  \
        }                                                                      \
    } while(0)

    {
        float4 bv[4];
        A_LOAD(smb, 0);
        asm volatile("cp.async.commit_group;");
        AB_LDG(bv, 0, 0);
        AB_STS(bv, sm, 0);
        AB_LDG(bv, 0, 1);
        AB_STS(bv, sm, 1);
        asm volatile("cp.async.wait_group 0;" ::: "memory");
        __syncthreads();
    }

    int buf = 0;
    for (int s = 0; s < S; ++s) {
        const unsigned cb = smb + buf * BUFSZ;
        const unsigned nb = smb + (buf ^ 1) * BUFSZ;
        char* nbg = sm + (buf ^ 1) * BUFSZ;
        const int k0n = (s + 1) * BK;
        const bool more = (s + 1 < S);
        float4 bv[4];

        if (more) {
            AB_LDG(bv, k0n, 0);
            A_LOAD(nb, k0n);
            asm volatile("cp.async.commit_group;");
        }
        A_COMPUTE(cb, 0);
        if (more) {
            AB_STS(bv, nbg, 0);
            AB_LDG(bv, k0n, 1);
        }
        A_COMPUTE(cb, 32);
        if (more) {
            AB_STS(bv, nbg, 1);
            asm volatile("cp.async.wait_group 0;" ::: "memory");
        }
        __syncthreads();
        buf ^= 1;
    }

    // fused SwiGLU epilogue -> fp16 act
    const int gq = lane >> 2, tau = lane & 3;
    #pragma unroll
    for (int mf = 0; mf < 4; ++mf) {
        #pragma unroll
        for (int u = 0; u < 2; ++u) {
            int col = n0 + wn16 + u*8 + tau*2;
            int r0 = wm + mf*16 + gq;
            int r1 = r0 + 8;
            if (r0 < rows) {
                float a0 = acc1[mf][u][0], a1 = acc1[mf][u][1];
                float v0 = a0 / (1.f + expf(-a0)) * acc3[mf][u][0];
                float v1 = a1 / (1.f + expf(-a1)) * acc3[mf][u][1];
                unsigned h01; cvt2h(h01, v1, v0);
                *(unsigned*)(g_acth + (size_t)(base_pos + mtile*BM + r0) * II + col) = h01;
            }
            if (r1 < rows) {
                float a0 = acc1[mf][u][2], a1 = acc1[mf][u][3];
                float v0 = a0 / (1.f + expf(-a0)) * acc3[mf][u][2];
                float v1 = a1 / (1.f + expf(-a1)) * acc3[mf][u][3];
                unsigned h01; cvt2h(h01, v1, v0);
                *(unsigned*)(g_acth + (size_t)(base_pos + mtile*BM + r1) * II + col) = h01;
            }
        }
    }
}

// ---------------- phase B: R11 GEMM (act @ W2^T -> pairout) ----------------
__global__ void __launch_bounds__(NTHR, 2) gemmB_kernel(
    const float* __restrict__ w2, const float* __restrict__ ws2)
{
    const int g     = blockIdx.z;
    const int mtile = blockIdx.x;
    const int n0    = blockIdx.y * BN;

    int m_count, base_pos;
    if (g < EE) { m_count = g_counts[g]; base_pos = g_offsets[g]; }
    else        { m_count = TT;          base_pos = NROUTED; }
    if (mtile * BM >= m_count) return;
    const int rows = min(BM, m_count - mtile * BM);

    const float* W = (g < EE) ? (w2 + (size_t)g * (size_t)II * HH) : ws2;
    float* C = g_pairout;

    extern __shared__ char sm[];
    const unsigned smb = (unsigned)__cvta_generic_to_shared(sm);
    const int tid = threadIdx.x;
    const int apos0 = base_pos + mtile*BM;

    const int S = II / BK;
    const int warp = tid >> 5, lane = tid & 31;
    const int wm = (warp & 1) * 64;
    const int wn = (warp >> 1) * 32;
    const int l15 = lane & 15, lh = lane >> 4;

    float acc[4][4][4];
    #pragma unroll
    for (int i = 0; i < 4; ++i)
        #pragma unroll
        for (int j = 0; j < 4; ++j)
            #pragma unroll
            for (int q = 0; q < 4; ++q) acc[i][j][q] = 0.f;

    #define B_LOAD_A(dstb, k0) do {                                            \
        _Pragma("unroll")                                                      \
        for (int t = 0; t < 4; ++t) {                                          \
            int c = tid + t*NTHR;                                              \
            int row = c >> 3, ch = c & 7;                                      \
            int rr = min(row, rows - 1);                                       \
            const __half* srcp = g_acth + (size_t)(apos0 + rr)*II + (k0) + ch*8; \
            cp16((dstb) + OFF_A + row*ROWB + ch*16, srcp);                     \
        }                                                                      \
    } while(0)
    #define B_LDG(bv, k0, h) do {                                              \
        _Pragma("unroll")                                                      \
        for (int t = 0; t < 4; ++t) {                                          \
            int c = tid + t*NTHR;                                              \
            int row = c >> 3, f4 = c & 7;                                      \
            (bv)[t] = *(const float4*)(W + (size_t)(n0+row)*II + (k0) + (h)*32 + f4*4); \
        }                                                                      \
    } while(0)
    #define B_STS(bv, dstg, h) do {                                            \
        _Pragma("unroll")                                                      \
        for (int t = 0; t < 4; ++t) {                                          \
            int c = tid + t*NTHR;                                              \
            int row = c >> 3, f4 = c & 7;                                      \
            unsigned h01, h23;                                                 \
            cvt2h(h01, (bv)[t].y, (bv)[t].x);                                  \
            cvt2h(h23, (bv)[t].w, (bv)[t].z);                                  \
            *(uint2*)((dstg) + OFF_B + row*ROWB + (h)*64 + f4*8) = make_uint2(h01, h23); \
        }                                                                      \
    } while(0)
    #define B_COMPUTE(cb, kk0) do {                                            \
        _Pragma("unroll")                                                      \
        for (int kk = (kk0); kk < (kk0) + 32; kk += 16) {                      \
            unsigned bh[2][4];                                                 \
            _Pragma("unroll")                                                  \
            for (int nf2 = 0; nf2 < 2; ++nf2) {                                \
                unsigned addr = (cb) + OFF_B + (wn + nf2*16 + l15)*ROWB + (kk + lh*8)*2; \
                ldsm4(bh[nf2][0], bh[nf2][1], bh[nf2][2], bh[nf2][3], addr);   \
            }                                                                  \
            _Pragma("unroll")                                                  \
            for (int mf = 0; mf < 4; ++mf) {                                   \
                unsigned ah[4];                                                \
                unsigned addr = (cb) + OFF_A + (wm + mf*16 + l15)*ROWB + (kk + lh*8)*2; \
                ldsm4(ah[0], ah[1], ah[2], ah[3], addr);                       \
                _Pragma("unroll")                                              \
                for (int nf2 = 0; nf2 < 2; ++nf2) {                            \
                    _Pragma("unroll")                                          \
                    for (int u = 0; u < 2; ++u)                                \
                        mma16816(acc[mf][nf2*2 + u], ah, bh[nf2][u], bh[nf2][2 + u]); \
                }                                                              \
            }                                                                  \
        }                                                                      \
    } while(0)

    {
        float4 bv[4];
        B_LOAD_A(smb, 0);
        asm volatile("cp.async.commit_group;");
        B_LDG(bv, 0, 0);
        B_STS(bv, sm, 0);
        B_LDG(bv, 0, 1);
        B_STS(bv, sm, 1);
        asm volatile("cp.async.wait_group 0;" ::: "memory");
        __syncthreads();
    }

    int buf = 0;
    for (int s = 0; s < S; ++s) {
        const unsigned cb = smb + buf * BUFSZ;
        const unsigned nb = smb + (buf ^ 1) * BUFSZ;
        char* nbg = sm + (buf ^ 1) * BUFSZ;
        const int k0n = (s + 1) * BK;
        const bool more = (s + 1 < S);
        float4 bv[4];

        if (more) {
            B_LDG(bv, k0n, 0);
            B_LOAD_A(nb, k0n);
            asm volatile("cp.async.commit_group;");
        }
        B_COMPUTE(cb, 0);
        if (more) {
            B_STS(bv, nbg, 0);
            B_LDG(bv, k0n, 1);
        }
        B_COMPUTE(cb, 32);
        if (more) {
            B_STS(bv, nbg, 1);
            asm volatile("cp.async.wait_group 0;" ::: "memory");
        }
        __syncthreads();
        buf ^= 1;
    }

    const int gq = lane >> 2, tau = lane & 3;
    #pragma unroll
    for (int mf = 0; mf < 4; ++mf) {
        #pragma unroll
        for (int nf = 0; nf < 4; ++nf) {
            int col = n0 + wn + nf*8 + tau*2;
            int r0 = wm + mf*16 + gq;
            int r1 = r0 + 8;
            if (r0 < rows) {
                float* d = C + (size_t)(apos0 + r0) * HH + col;
                d[0] = acc[mf][nf][0]; d[1] = acc[mf][nf][1];
            }
            if (r1 < rows) {
                float* d = C + (size_t)(apos0 + r1) * HH + col;
                d[0] = acc[mf][nf][2]; d[1] = acc[mf][nf][3];
            }
        }
    }
}

// ---------------- combine ----------------
__global__ __launch_bounds__(256) void combine_kernel(float* __restrict__ out)
{
    const int t = blockIdx.x;
    const int tid = threadIdx.x;
    __shared__ float w[TOPK];
    __shared__ int   pos[TOPK];
    if (tid < TOPK) {
        w[tid]   = g_topk_w[t*TOPK + tid];
        pos[tid] = g_pair_pos[t*TOPK + tid];
    }
    __syncthreads();
    const float4* sh = (const float4*)(g_pairout + (size_t)(NROUTED + t) * HH);
    const float4* p0 = (const float4*)(g_pairout + (size_t)pos[0] * HH);
    const float4* p1 = (const float4*)(g_pairout + (size_t)pos[1] * HH);
    const float4* p2 = (const float4*)(g_pairout + (size_t)pos[2] * HH);
    const float4* p3 = (const float4*)(g_pairout + (size_t)pos[3] * HH);
    float4* o = (float4*)(out + (size_t)t * HH);
    const float w0=w[0], w1=w[1], w2=w[2], w3=w[3];
    #pragma unroll
    for (int it = 0; it < HH/4/256; ++it) {
        int i = tid + it*256;
        float4 acc = sh[i];
        float4 v0 = p0[i], v1 = p1[i], v2 = p2[i], v3 = p3[i];
        acc.x += w0*v0.x + w1*v1.x + w2*v2.x + w3*v3.x;
        acc.y += w0*v0.y + w1*v1.y + w2*v2.y + w3*v3.y;
        acc.z += w0*v0.z + w1*v1.z + w2*v2.z + w3*v3.z;
        acc.w += w0*v0.w + w1*v1.w + w2*v2.w + w3*v3.w;
        o[i] = acc;
    }
}

// ---------------- launch ----------------
extern "C" void kernel_launch(void* const* d_in, const int* in_sizes, int n_in,
                              void* d_out, int out_size)
{
    const float* x    = (const float*)d_in[0];
    const float* gw   = (const float*)d_in[1];
    const float* bias = (const float*)d_in[2];
    const float* w1   = (const float*)d_in[3];
    const float* w3   = (const float*)d_in[4];
    const float* w2   = (const float*)d_in[5];
    const float* ws1  = (const float*)d_in[6];
    const float* ws3  = (const float*)d_in[7];
    const float* ws2  = (const float*)d_in[8];
    float* out = (float*)d_out;

    cudaFuncSetAttribute(gemmA_kernel, cudaFuncAttributeMaxDynamicSharedMemorySize, SMEM_DYN);
    cudaFuncSetAttribute(gemmB_kernel, cudaFuncAttributeMaxDynamicSharedMemorySize, SMEM_DYN);

    zero_kernel<<<1, 64>>>();
    gate_kernel<<<TT/4, 256>>>(x, gw, bias);
    offsets_kernel<<<1, 32>>>();
    scatter_kernel<<<TT/256, 256>>>();

    // phase A: act = silu(X@W1^T) * (X@W3^T), fused epilogue; 16 n-blocks of 64
    gemmA_kernel<<<dim3(16, 16, EE+1), NTHR, SMEM_DYN>>>(w1, ws1, w3, ws3);
    // phase B: pairout = act@W2^T
    gemmB_kernel<<<dim3(16, 16, EE+1), NTHR, SMEM_DYN>>>(w2, ws2);
    combine_kernel<<<TT, 256>>>(out);
}

// round 14
// speedup vs baseline: 1.0017x; 1.0017x over previous
#include <cuda_runtime.h>
#include <cuda_fp16.h>
#include <math.h>
#include <stdint.h>

#define TT 2048
#define HH 2048
#define II 1024
#define EE 32
#define TOPK 4
#define NROUTED (TT*TOPK)
#define NPAIRS  (NROUTED + TT)

// GEMM tiling: BM=128, BN=128, BK=64, 256 thr, 2 CTA/SM
#define BM 128
#define BN 128
#define BK 64
#define NTHR 256
#define ROWB 144                   // 64 fp16 = 128B + 16B pad
#define OFF_A 0
#define OFF_B 18432                // 128*144
#define BUFSZ 36864
#define SMEM_DYN (2*BUFSZ)

// ---------------- device scratch ----------------
__device__ int   g_counts[EE];
__device__ int   g_cursor[EE];
__device__ int   g_offsets[EE];
__device__ int   g_topk_idx[NROUTED];
__device__ float g_topk_w[NROUTED];
__device__ int   g_pair_token[NROUTED];
__device__ int   g_pair_pos[NROUTED];
__device__ __half g_xh[(size_t)TT*HH];
__device__ float g_C1[(size_t)NPAIRS*II];
__device__ float g_C3[(size_t)NPAIRS*II];
__device__ __half g_acth[(size_t)NPAIRS*II];
__device__ float g_pairout[(size_t)NPAIRS*HH];

// ---------------- helpers ----------------
__device__ __forceinline__ void cvt2h(unsigned &r, float hi_elem, float lo_elem) {
    asm("cvt.rn.f16x2.f32 %0, %1, %2;" : "=r"(r) : "f"(hi_elem), "f"(lo_elem));
}
__device__ __forceinline__ void ldsm4(unsigned &r0, unsigned &r1, unsigned &r2, unsigned &r3,
                                      unsigned addr) {
    asm volatile("ldmatrix.sync.aligned.m8n8.x4.shared.b16 {%0,%1,%2,%3}, [%4];"
                 : "=r"(r0), "=r"(r1), "=r"(r2), "=r"(r3) : "r"(addr));
}
__device__ __forceinline__ void mma16816(float* c, const unsigned* a, unsigned b0, unsigned b1) {
    asm volatile("mma.sync.aligned.m16n8k16.row.col.f32.f16.f16.f32 "
                 "{%0,%1,%2,%3}, {%4,%5,%6,%7}, {%8,%9}, {%0,%1,%2,%3};"
                 : "+f"(c[0]), "+f"(c[1]), "+f"(c[2]), "+f"(c[3])
                 : "r"(a[0]), "r"(a[1]), "r"(a[2]), "r"(a[3]), "r"(b0), "r"(b1));
}
__device__ __forceinline__ void cp16(unsigned dst, const void* src) {
    asm volatile("cp.async.cg.shared.global [%0], [%1], 16;" :: "r"(dst), "l"(src));
}

// ---------------- small kernels ----------------
__global__ void zero_kernel() {
    int i = threadIdx.x;
    if (i < EE) { g_counts[i] = 0; g_cursor[i] = 0; }
}
__global__ void offsets_kernel() {
    if (threadIdx.x == 0) {
        int s = 0;
        for (int e = 0; e < EE; ++e) { g_offsets[e] = s; s += g_counts[e]; }
    }
}
__global__ void scatter_kernel() {
    int t = blockIdx.x * blockDim.x + threadIdx.x;
    if (t >= TT) return;
    #pragma unroll
    for (int j = 0; j < TOPK; ++j) {
        int e = g_topk_idx[t*TOPK + j];
        int pos = g_offsets[e] + atomicAdd(&g_cursor[e], 1);
        g_pair_token[pos] = t;
        g_pair_pos[t*TOPK + j] = pos;
    }
}
__global__ __launch_bounds__(256) void act_kernel() {
    size_t i4 = (size_t)blockIdx.x * 256 + threadIdx.x;
    float4 a = ((const float4*)g_C1)[i4];
    float4 b = ((const float4*)g_C3)[i4];
    float v0 = a.x / (1.f + expf(-a.x)) * b.x;
    float v1 = a.y / (1.f + expf(-a.y)) * b.y;
    float v2 = a.z / (1.f + expf(-a.z)) * b.z;
    float v3 = a.w / (1.f + expf(-a.w)) * b.w;
    unsigned h01, h23;
    cvt2h(h01, v1, v0);
    cvt2h(h23, v3, v2);
    ((uint2*)g_acth)[i4] = make_uint2(h01, h23);
}

// ---------------- gate + routing + x->fp16 (fused) ----------------
__global__ __launch_bounds__(256) void gate_kernel(
        const float* __restrict__ x, const float* __restrict__ gw,
        const float* __restrict__ bias)
{
    __shared__ float xs[4][HH];
    __shared__ float logits_s[4][EE];
    __shared__ float bias_s[EE];
    int tid = threadIdx.x;
    int t0  = blockIdx.x * 4;
    const float4* xg  = (const float4*)(x + (size_t)t0 * HH);
    float4*       xs4 = (float4*)&xs[0][0];
    #pragma unroll
    for (int i = 0; i < 8; ++i) xs4[tid + i*256] = xg[tid + i*256];
    if (tid < EE) bias_s[tid] = bias[tid];
    __syncthreads();

    // fused convx: fp16 copy of these 4 rows
    {
        uint2* dst = (uint2*)(g_xh + (size_t)t0 * HH);
        #pragma unroll
        for (int i = 0; i < 8; ++i) {
            float4 v = xs4[tid + i*256];
            unsigned h01, h23;
            cvt2h(h01, v.y, v.x);
            cvt2h(h23, v.w, v.z);
            dst[tid + i*256] = make_uint2(h01, h23);
        }
    }

    int warp = tid >> 5, lane = tid & 31;
    #pragma unroll
    for (int ei = 0; ei < 4; ++ei) {
        int e = warp*4 + ei;
        const float* gr = gw + (size_t)e * HH;
        float a0=0.f, a1=0.f, a2=0.f, a3=0.f;
        for (int h = lane; h < HH; h += 32) {
            float g = gr[h];
            a0 = fmaf(g, xs[0][h], a0); a1 = fmaf(g, xs[1][h], a1);
            a2 = fmaf(g, xs[2][h], a2); a3 = fmaf(g, xs[3][h], a3);
        }
        #pragma unroll
        for (int off = 16; off; off >>= 1) {
            a0 += __shfl_xor_sync(0xffffffffu, a0, off);
            a1 += __shfl_xor_sync(0xffffffffu, a1, off);
            a2 += __shfl_xor_sync(0xffffffffu, a2, off);
            a3 += __shfl_xor_sync(0xffffffffu, a3, off);
        }
        if (lane == 0) {
            logits_s[0][e] = a0; logits_s[1][e] = a1;
            logits_s[2][e] = a2; logits_s[3][e] = a3;
        }
    }
    __syncthreads();
    if (warp < 4) {
        int t = t0 + warp;
        float logit = logits_s[warp][lane];
        float s   = 1.f / (1.f + expf(-logit));
        float sfc = s + bias_s[lane];
        float m1 = sfc, m2 = -INFINITY;
        #pragma unroll
        for (int off = 4; off >= 1; off >>= 1) {
            float o1 = __shfl_xor_sync(0xffffffffu, m1, off);
            float o2 = __shfl_xor_sync(0xffffffffu, m2, off);
            float hi = fmaxf(m1, o1);
            float lo = fmaxf(fminf(m1, o1), fmaxf(m2, o2));
            m1 = hi; m2 = lo;
        }
        float gs = m1 + m2;
        float gv[4];
        gv[0] = __shfl_sync(0xffffffffu, gs, 0);
        gv[1] = __shfl_sync(0xffffffffu, gs, 8);
        gv[2] = __shfl_sync(0xffffffffu, gs, 16);
        gv[3] = __shfl_sync(0xffffffffu, gs, 24);
        int b1 = 0; float v1 = gv[0];
        #pragma unroll
        for (int gg = 1; gg < 4; ++gg) if (gv[gg] > v1) { v1 = gv[gg]; b1 = gg; }
        int b2 = -1; float v2 = -INFINITY;
        #pragma unroll
        for (int gg = 0; gg < 4; ++gg) {
            if (gg == b1) continue;
            if (gv[gg] > v2) { v2 = gv[gg]; b2 = gg; }
        }
        int mygrp = lane >> 3;
        float val = (mygrp == b1 || mygrp == b2) ? sfc : 0.0f;
        int sel_i[TOPK]; float sel_w[TOPK];
        float cur = val;
        #pragma unroll
        for (int j = 0; j < TOPK; ++j) {
            float bv = cur; int bi = lane;
            #pragma unroll
            for (int off = 16; off >= 1; off >>= 1) {
                float ov = __shfl_xor_sync(0xffffffffu, bv, off);
                int   oi = __shfl_xor_sync(0xffffffffu, bi, off);
                if (ov > bv || (ov == bv && oi < bi)) { bv = ov; bi = oi; }
            }
            sel_i[j] = bi;
            sel_w[j] = __shfl_sync(0xffffffffu, s, bi);
            if (lane == bi) cur = -INFINITY;
        }
        if (lane == 0) {
            float sum = sel_w[0] + sel_w[1] + sel_w[2] + sel_w[3];
            float scale = 2.5f / (sum + 1e-20f);
            #pragma unroll
            for (int j = 0; j < TOPK; ++j) {
                g_topk_idx[t*TOPK + j] = sel_i[j];
                g_topk_w[t*TOPK + j]   = sel_w[j] * scale;
                atomicAdd(&g_counts[sel_i[j]], 1);
            }
        }
    }
}

// ---------------- grouped fp16 GEMM: BK=64, half-batched B convert (R11) ----------------
__global__ void __launch_bounds__(NTHR, 2) gemm_kernel(
    const __half* __restrict__ A, int lda,
    const float* __restrict__ Wra, const float* __restrict__ Wsa,
    const float* __restrict__ Wrb, const float* __restrict__ Wsb,
    int Kdim, int ybnd, float* __restrict__ Ca, float* __restrict__ Cb,
    int ldc, int gather)
{
    const int g     = blockIdx.z;
    const int mtile = blockIdx.x;
    const int y     = blockIdx.y;

    int m_count, base_pos;
    if (g < EE) { m_count = g_counts[g]; base_pos = g_offsets[g]; }
    else        { m_count = TT;          base_pos = NROUTED; }
    if (mtile * BM >= m_count) return;
    const int rows = min(BM, m_count - mtile * BM);

    const size_t wsz = (size_t)II * HH;
    const float* W;
    float* C;
    int n0;
    if (y < ybnd) {
        W = (g < EE) ? (Wra + (size_t)g * wsz) : Wsa;
        C = Ca; n0 = y * BN;
    } else {
        W = (g < EE) ? (Wrb + (size_t)g * wsz) : Wsb;
        C = Cb; n0 = (y - ybnd) * BN;
    }

    extern __shared__ char sm[];
    __shared__ int s_toks[BM];
    const unsigned smb = (unsigned)__cvta_generic_to_shared(sm);

    const int tid = threadIdx.x;
    if (tid < BM) {
        int r = min(tid, rows - 1);
        int pos = base_pos + mtile*BM + r;
        s_toks[tid] = gather ? ((g < EE) ? g_pair_token[pos] : (mtile*BM + r)) : pos;
    }
    __syncthreads();

    const int S = Kdim / BK;
    const int warp = tid >> 5, lane = tid & 31;
    const int wm = (warp & 1) * 64;
    const int wn = (warp >> 1) * 32;
    const int l15 = lane & 15, lh = lane >> 4;

    float acc[4][4][4];
    #pragma unroll
    for (int i = 0; i < 4; ++i)
        #pragma unroll
        for (int j = 0; j < 4; ++j)
            #pragma unroll
            for (int q = 0; q < 4; ++q) acc[i][j][q] = 0.f;

    #define LOAD_A(dstb, k0) do {                                            \
        _Pragma("unroll")                                                    \
        for (int t = 0; t < 4; ++t) {                                        \
            int c = tid + t*NTHR;                                            \
            int row = c >> 3, ch = c & 7;                                    \
            const __half* srcp = A + (size_t)s_toks[row]*lda + (k0) + ch*8;  \
            cp16((dstb) + OFF_A + row*ROWB + ch*16, srcp);                   \
        }                                                                    \
    } while(0)
    #define LDG_B(bv, k0, h) do {                                            \
        _Pragma("unroll")                                                    \
        for (int t = 0; t < 4; ++t) {                                        \
            int c = tid + t*NTHR;                                            \
            int row = c >> 3, f4 = c & 7;                                    \
            (bv)[t] = *(const float4*)(W + (size_t)(n0+row)*Kdim + (k0) + (h)*32 + f4*4); \
        }                                                                    \
    } while(0)
    #define STS_B(bv, dstg, h) do {                                          \
        _Pragma("unroll")                                                    \
        for (int t = 0; t < 4; ++t) {                                        \
            int c = tid + t*NTHR;                                            \
            int row = c >> 3, f4 = c & 7;                                    \
            unsigned h01, h23;                                               \
            cvt2h(h01, (bv)[t].y, (bv)[t].x);                                \
            cvt2h(h23, (bv)[t].w, (bv)[t].z);                                \
            *(uint2*)((dstg) + OFF_B + row*ROWB + (h)*64 + f4*8) = make_uint2(h01, h23); \
        }                                                                    \
    } while(0)
    #define COMPUTE_HALF(cb, kk0) do {                                       \
        _Pragma("unroll")                                                    \
        for (int kk = (kk0); kk < (kk0) + 32; kk += 16) {                    \
            unsigned bh[2][4];                                               \
            _Pragma("unroll")                                                \
            for (int nf2 = 0; nf2 < 2; ++nf2) {                              \
                unsigned addr = (cb) + OFF_B + (wn + nf2*16 + l15)*ROWB + (kk + lh*8)*2; \
                ldsm4(bh[nf2][0], bh[nf2][1], bh[nf2][2], bh[nf2][3], addr); \
            }                                                                \
            _Pragma("unroll")                                                \
            for (int mf = 0; mf < 4; ++mf) {                                 \
                unsigned ah[4];                                              \
                unsigned addr = (cb) + OFF_A + (wm + mf*16 + l15)*ROWB + (kk + lh*8)*2; \
                ldsm4(ah[0], ah[1], ah[2], ah[3], addr);                     \
                _Pragma("unroll")                                            \
                for (int nf2 = 0; nf2 < 2; ++nf2) {                          \
                    _Pragma("unroll")                                        \
                    for (int u = 0; u < 2; ++u)                              \
                        mma16816(acc[mf][nf2*2 + u], ah, bh[nf2][u], bh[nf2][2 + u]); \
                }                                                            \
            }                                                                \
        }                                                                    \
    } while(0)

    {
        float4 bv[4];
        LOAD_A(smb, 0);
        asm volatile("cp.async.commit_group;");
        LDG_B(bv, 0, 0);
        STS_B(bv, sm, 0);
        LDG_B(bv, 0, 1);
        STS_B(bv, sm, 1);
        asm volatile("cp.async.wait_group 0;" ::: "memory");
        __syncthreads();
    }

    int buf = 0;
    for (int s = 0; s < S; ++s) {
        const unsigned cb = smb + buf * BUFSZ;
        const unsigned nb = smb + (buf ^ 1) * BUFSZ;
        char* nbg = sm + (buf ^ 1) * BUFSZ;
        const int k0n = (s + 1) * BK;
        const bool more = (s + 1 < S);
        float4 bv[4];

        if (more) {
            LDG_B(bv, k0n, 0);
            LOAD_A(nb, k0n);
            asm volatile("cp.async.commit_group;");
        }
        COMPUTE_HALF(cb, 0);
        if (more) {
            STS_B(bv, nbg, 0);
            LDG_B(bv, k0n, 1);
        }
        COMPUTE_HALF(cb, 32);
        if (more) {
            STS_B(bv, nbg, 1);
            asm volatile("cp.async.wait_group 0;" ::: "memory");
        }
        __syncthreads();
        buf ^= 1;
    }

    const int gq = lane >> 2, tau = lane & 3;
    #pragma unroll
    for (int mf = 0; mf < 4; ++mf) {
        #pragma unroll
        for (int nf = 0; nf < 4; ++nf) {
            int col = n0 + wn + nf*8 + tau*2;
            int r0 = wm + mf*16 + gq;
            int r1 = r0 + 8;
            if (r0 < rows) {
                float* d = C + (size_t)(base_pos + mtile*BM + r0) * ldc + col;
                d[0] = acc[mf][nf][0]; d[1] = acc[mf][nf][1];
            }
            if (r1 < rows) {
                float* d = C + (size_t)(base_pos + mtile*BM + r1) * ldc + col;
                d[0] = acc[mf][nf][2]; d[1] = acc[mf][nf][3];
            }
        }
    }
}

// ---------------- combine ----------------
__global__ __launch_bounds__(256) void combine_kernel(float* __restrict__ out)
{
    const int t = blockIdx.x;
    const int tid = threadIdx.x;
    __shared__ float w[TOPK];
    __shared__ int   pos[TOPK];
    if (tid < TOPK) {
        w[tid]   = g_topk_w[t*TOPK + tid];
        pos[tid] = g_pair_pos[t*TOPK + tid];
    }
    __syncthreads();
    const float4* sh = (const float4*)(g_pairout + (size_t)(NROUTED + t) * HH);
    const float4* p0 = (const float4*)(g_pairout + (size_t)pos[0] * HH);
    const float4* p1 = (const float4*)(g_pairout + (size_t)pos[1] * HH);
    const float4* p2 = (const float4*)(g_pairout + (size_t)pos[2] * HH);
    const float4* p3 = (const float4*)(g_pairout + (size_t)pos[3] * HH);
    float4* o = (float4*)(out + (size_t)t * HH);
    const float w0=w[0], w1=w[1], w2=w[2], w3=w[3];
    #pragma unroll
    for (int it = 0; it < HH/4/256; ++it) {
        int i = tid + it*256;
        float4 acc = sh[i];
        float4 v0 = p0[i], v1 = p1[i], v2 = p2[i], v3 = p3[i];
        acc.x += w0*v0.x + w1*v1.x + w2*v2.x + w3*v3.x;
        acc.y += w0*v0.y + w1*v1.y + w2*v2.y + w3*v3.y;
        acc.z += w0*v0.z + w1*v1.z + w2*v2.z + w3*v3.z;
        acc.w += w0*v0.w + w1*v1.w + w2*v2.w + w3*v3.w;
        o[i] = acc;
    }
}

// ---------------- launch ----------------
extern "C" void kernel_launch(void* const* d_in, const int* in_sizes, int n_in,
                              void* d_out, int out_size)
{
    const float* x    = (const float*)d_in[0];
    const float* gw   = (const float*)d_in[1];
    const float* bias = (const float*)d_in[2];
    const float* w1   = (const float*)d_in[3];
    const float* w3   = (const float*)d_in[4];
    const float* w2   = (const float*)d_in[5];
    const float* ws1  = (const float*)d_in[6];
    const float* ws3  = (const float*)d_in[7];
    const float* ws2  = (const float*)d_in[8];
    float* out = (float*)d_out;

    cudaFuncSetAttribute(gemm_kernel, cudaFuncAttributeMaxDynamicSharedMemorySize, SMEM_DYN);

    zero_kernel<<<1, 64>>>();
    gate_kernel<<<TT/4, 256>>>(x, gw, bias);
    offsets_kernel<<<1, 32>>>();
    scatter_kernel<<<TT/256, 256>>>();

    __half *xh, *ah;
    cudaGetSymbolAddress((void**)&xh, g_xh);
    cudaGetSymbolAddress((void**)&ah, g_acth);
    float *c1, *c3, *po;
    cudaGetSymbolAddress((void**)&c1, g_C1);
    cudaGetSymbolAddress((void**)&c3, g_C3);
    cudaGetSymbolAddress((void**)&po, g_pairout);

    // phase A: C1 = X@W1^T (y<8), C3 = X@W3^T (y>=8); K=HH
    gemm_kernel<<<dim3(16, 16, EE+1), NTHR, SMEM_DYN>>>(
        xh, HH, w1, ws1, w3, ws3, HH, 8, c1, c3, II, 1);
    act_kernel<<<(int)((size_t)NPAIRS*II/4/256), 256>>>();
    // phase B: pairout = act@W2^T; K=II
    gemm_kernel<<<dim3(16, 16, EE+1), NTHR, SMEM_DYN>>>(
        ah, II, w2, ws2, w2, ws2, II, 16, po, po, HH, 0);
    combine_kernel<<<TT, 256>>>(out);
}

// round 15
// speedup vs baseline: 1.4345x; 1.4321x over previous
#include <cuda_runtime.h>
#include <cuda_fp16.h>
#include <math.h>
#include <stdint.h>

#define TT 2048
#define HH 2048
#define II 1024
#define EE 32
#define TOPK 4
#define NROUTED (TT*TOPK)
#define NPAIRS  (NROUTED + TT)

// GEMM tiling: BM=128, BN=128, BK=64, 256 thr, 2 CTA/SM
#define BM 128
#define BN 128
#define BK 64
#define NTHR 256
#define ROWB 144                   // 64 fp16 = 128B + 16B pad
#define OFF_A 0
#define OFF_B 18432                // 128*144
#define BUFSZ 36864
#define SMEM_DYN (2*BUFSZ)

// ---------------- device scratch ----------------
__device__ int   g_counts[EE];
__device__ int   g_cursor[EE];
__device__ int   g_offsets[EE];
__device__ int   g_topk_idx[NROUTED];
__device__ float g_topk_w[NROUTED];
__device__ int   g_pair_token[NROUTED];
__device__ int   g_pair_pos[NROUTED];
__device__ __half g_xh[(size_t)TT*HH];
__device__ float g_C1[(size_t)NPAIRS*II];
__device__ float g_C3[(size_t)NPAIRS*II];
__device__ __half g_acth[(size_t)NPAIRS*II];
__device__ float g_pairout[(size_t)NPAIRS*HH];

// ---------------- helpers ----------------
__device__ __forceinline__ void cvt2h(unsigned &r, float hi_elem, float lo_elem) {
    asm("cvt.rn.f16x2.f32 %0, %1, %2;" : "=r"(r) : "f"(hi_elem), "f"(lo_elem));
}
__device__ __forceinline__ void ldsm4(unsigned &r0, unsigned &r1, unsigned &r2, unsigned &r3,
                                      unsigned addr) {
    asm volatile("ldmatrix.sync.aligned.m8n8.x4.shared.b16 {%0,%1,%2,%3}, [%4];"
                 : "=r"(r0), "=r"(r1), "=r"(r2), "=r"(r3) : "r"(addr));
}
__device__ __forceinline__ void mma16816(float* c, const unsigned* a, unsigned b0, unsigned b1) {
    asm volatile("mma.sync.aligned.m16n8k16.row.col.f32.f16.f16.f32 "
                 "{%0,%1,%2,%3}, {%4,%5,%6,%7}, {%8,%9}, {%0,%1,%2,%3};"
                 : "+f"(c[0]), "+f"(c[1]), "+f"(c[2]), "+f"(c[3])
                 : "r"(a[0]), "r"(a[1]), "r"(a[2]), "r"(a[3]), "r"(b0), "r"(b1));
}
__device__ __forceinline__ void cp16(unsigned dst, const void* src) {
    asm volatile("cp.async.cg.shared.global [%0], [%1], 16;" :: "r"(dst), "l"(src));
}

// ---------------- small kernels ----------------
__global__ void zero_kernel() {
    int i = threadIdx.x;
    if (i < EE) { g_counts[i] = 0; g_cursor[i] = 0; }
}
__global__ void offsets_kernel() {
    if (threadIdx.x == 0) {
        int s = 0;
        for (int e = 0; e < EE; ++e) { g_offsets[e] = s; s += g_counts[e]; }
    }
}
__global__ void scatter_kernel() {
    int t = blockIdx.x * blockDim.x + threadIdx.x;
    if (t >= TT) return;
    #pragma unroll
    for (int j = 0; j < TOPK; ++j) {
        int e = g_topk_idx[t*TOPK + j];
        int pos = g_offsets[e] + atomicAdd(&g_cursor[e], 1);
        g_pair_token[pos] = t;
        g_pair_pos[t*TOPK + j] = pos;
    }
}
__global__ __launch_bounds__(256) void convx_kernel(const float* __restrict__ x) {
    int i = blockIdx.x * 256 + threadIdx.x;
    g_xh[i] = __float2half_rn(x[i]);
}
__global__ __launch_bounds__(256) void act_kernel() {
    size_t i4 = (size_t)blockIdx.x * 256 + threadIdx.x;
    float4 a = ((const float4*)g_C1)[i4];
    float4 b = ((const float4*)g_C3)[i4];
    float v0 = a.x / (1.f + expf(-a.x)) * b.x;
    float v1 = a.y / (1.f + expf(-a.y)) * b.y;
    float v2 = a.z / (1.f + expf(-a.z)) * b.z;
    float v3 = a.w / (1.f + expf(-a.w)) * b.w;
    unsigned h01, h23;
    cvt2h(h01, v1, v0);
    cvt2h(h23, v3, v2);
    ((uint2*)g_acth)[i4] = make_uint2(h01, h23);
}

// ---------------- gate + routing (proven) ----------------
__global__ __launch_bounds__(256) void gate_kernel(
        const float* __restrict__ x, const float* __restrict__ gw,
        const float* __restrict__ bias)
{
    __shared__ float xs[4][HH];
    __shared__ float logits_s[4][EE];
    __shared__ float bias_s[EE];
    int tid = threadIdx.x;
    int t0  = blockIdx.x * 4;
    const float4* xg  = (const float4*)(x + (size_t)t0 * HH);
    float4*       xs4 = (float4*)&xs[0][0];
    #pragma unroll
    for (int i = 0; i < 8; ++i) xs4[tid + i*256] = xg[tid + i*256];
    if (tid < EE) bias_s[tid] = bias[tid];
    __syncthreads();
    int warp = tid >> 5, lane = tid & 31;
    #pragma unroll
    for (int ei = 0; ei < 4; ++ei) {
        int e = warp*4 + ei;
        const float* gr = gw + (size_t)e * HH;
        float a0=0.f, a1=0.f, a2=0.f, a3=0.f;
        for (int h = lane; h < HH; h += 32) {
            float g = gr[h];
            a0 = fmaf(g, xs[0][h], a0); a1 = fmaf(g, xs[1][h], a1);
            a2 = fmaf(g, xs[2][h], a2); a3 = fmaf(g, xs[3][h], a3);
        }
        #pragma unroll
        for (int off = 16; off; off >>= 1) {
            a0 += __shfl_xor_sync(0xffffffffu, a0, off);
            a1 += __shfl_xor_sync(0xffffffffu, a1, off);
            a2 += __shfl_xor_sync(0xffffffffu, a2, off);
            a3 += __shfl_xor_sync(0xffffffffu, a3, off);
        }
        if (lane == 0) {
            logits_s[0][e] = a0; logits_s[1][e] = a1;
            logits_s[2][e] = a2; logits_s[3][e] = a3;
        }
    }
    __syncthreads();
    if (warp < 4) {
        int t = t0 + warp;
        float logit = logits_s[warp][lane];
        float s   = 1.f / (1.f + expf(-logit));
        float sfc = s + bias_s[lane];
        float m1 = sfc, m2 = -INFINITY;
        #pragma unroll
        for (int off = 4; off >= 1; off >>= 1) {
            float o1 = __shfl_xor_sync(0xffffffffu, m1, off);
            float o2 = __shfl_xor_sync(0xffffffffu, m2, off);
            float hi = fmaxf(m1, o1);
            float lo = fmaxf(fminf(m1, o1), fmaxf(m2, o2));
            m1 = hi; m2 = lo;
        }
        float gs = m1 + m2;
        float gv[4];
        gv[0] = __shfl_sync(0xffffffffu, gs, 0);
        gv[1] = __shfl_sync(0xffffffffu, gs, 8);
        gv[2] = __shfl_sync(0xffffffffu, gs, 16);
        gv[3] = __shfl_sync(0xffffffffu, gs, 24);
        int b1 = 0; float v1 = gv[0];
        #pragma unroll
        for (int gg = 1; gg < 4; ++gg) if (gv[gg] > v1) { v1 = gv[gg]; b1 = gg; }
        int b2 = -1; float v2 = -INFINITY;
        #pragma unroll
        for (int gg = 0; gg < 4; ++gg) {
            if (gg == b1) continue;
            if (gv[gg] > v2) { v2 = gv[gg]; b2 = gg; }
        }
        int mygrp = lane >> 3;
        float val = (mygrp == b1 || mygrp == b2) ? sfc : 0.0f;
        int sel_i[TOPK]; float sel_w[TOPK];
        float cur = val;
        #pragma unroll
        for (int j = 0; j < TOPK; ++j) {
            float bv = cur; int bi = lane;
            #pragma unroll
            for (int off = 16; off >= 1; off >>= 1) {
                float ov = __shfl_xor_sync(0xffffffffu, bv, off);
                int   oi = __shfl_xor_sync(0xffffffffu, bi, off);
                if (ov > bv || (ov == bv && oi < bi)) { bv = ov; bi = oi; }
            }
            sel_i[j] = bi;
            sel_w[j] = __shfl_sync(0xffffffffu, s, bi);
            if (lane == bi) cur = -INFINITY;
        }
        if (lane == 0) {
            float sum = sel_w[0] + sel_w[1] + sel_w[2] + sel_w[3];
            float scale = 2.5f / (sum + 1e-20f);
            #pragma unroll
            for (int j = 0; j < TOPK; ++j) {
                g_topk_idx[t*TOPK + j] = sel_i[j];
                g_topk_w[t*TOPK + j]   = sel_w[j] * scale;
                atomicAdd(&g_counts[sel_i[j]], 1);
            }
        }
    }
}

// ---------------- grouped fp16 GEMM: BK=64, half-batched B convert ----------------
__global__ void __launch_bounds__(NTHR, 2) gemm_kernel(
    const __half* __restrict__ A, int lda,
    const float* __restrict__ Wra, const float* __restrict__ Wsa,
    const float* __restrict__ Wrb, const float* __restrict__ Wsb,
    int Kdim, int ybnd, float* __restrict__ Ca, float* __restrict__ Cb,
    int ldc, int gather)
{
    const int g     = blockIdx.z;
    const int mtile = blockIdx.x;
    const int y     = blockIdx.y;

    int m_count, base_pos;
    if (g < EE) { m_count = g_counts[g]; base_pos = g_offsets[g]; }
    else        { m_count = TT;          base_pos = NROUTED; }
    if (mtile * BM >= m_count) return;
    const int rows = min(BM, m_count - mtile * BM);

    const size_t wsz = (size_t)II * HH;
    const float* W;
    float* C;
    int n0;
    if (y < ybnd) {
        W = (g < EE) ? (Wra + (size_t)g * wsz) : Wsa;
        C = Ca; n0 = y * BN;
    } else {
        W = (g < EE) ? (Wrb + (size_t)g * wsz) : Wsb;
        C = Cb; n0 = (y - ybnd) * BN;
    }

    extern __shared__ char sm[];
    __shared__ int s_toks[BM];
    const unsigned smb = (unsigned)__cvta_generic_to_shared(sm);

    const int tid = threadIdx.x;
    if (tid < BM) {
        int r = min(tid, rows - 1);
        int pos = base_pos + mtile*BM + r;
        s_toks[tid] = gather ? ((g < EE) ? g_pair_token[pos] : (mtile*BM + r)) : pos;
    }
    __syncthreads();

    const int S = Kdim / BK;
    const int warp = tid >> 5, lane = tid & 31;
    const int wm = (warp & 1) * 64;
    const int wn = (warp >> 1) * 32;
    const int l15 = lane & 15, lh = lane >> 4;

    float acc[4][4][4];
    #pragma unroll
    for (int i = 0; i < 4; ++i)
        #pragma unroll
        for (int j = 0; j < 4; ++j)
            #pragma unroll
            for (int q = 0; q < 4; ++q) acc[i][j][q] = 0.f;

    #define LOAD_A(dstb, k0) do {                                            \
        _Pragma("unroll")                                                    \
        for (int t = 0; t < 4; ++t) {                                        \
            int c = tid + t*NTHR;                                            \
            int row = c >> 3, ch = c & 7;                                    \
            const __half* srcp = A + (size_t)s_toks[row]*lda + (k0) + ch*8;  \
            cp16((dstb) + OFF_A + row*ROWB + ch*16, srcp);                   \
        }                                                                    \
    } while(0)
    #define LDG_B(bv, k0, h) do {                                            \
        _Pragma("unroll")                                                    \
        for (int t = 0; t < 4; ++t) {                                        \
            int c = tid + t*NTHR;                                            \
            int row = c >> 3, f4 = c & 7;                                    \
            (bv)[t] = *(const float4*)(W + (size_t)(n0+row)*Kdim + (k0) + (h)*32 + f4*4); \
        }                                                                    \
    } while(0)
    #define STS_B(bv, dstg, h) do {                                          \
        _Pragma("unroll")                                                    \
        for (int t = 0; t < 4; ++t) {                                        \
            int c = tid + t*NTHR;                                            \
            int row = c >> 3, f4 = c & 7;                                    \
            unsigned h01, h23;                                               \
            cvt2h(h01, (bv)[t].y, (bv)[t].x);                                \
            cvt2h(h23, (bv)[t].w, (bv)[t].z);                                \
            *(uint2*)((dstg) + OFF_B + row*ROWB + (h)*64 + f4*8) = make_uint2(h01, h23); \
        }                                                                    \
    } while(0)
    #define COMPUTE_HALF(cb, kk0) do {                                       \
        _Pragma("unroll")                                                    \
        for (int kk = (kk0); kk < (kk0) + 32; kk += 16) {                    \
            unsigned bh[2][4];                                               \
            _Pragma("unroll")                                                \
            for (int nf2 = 0; nf2 < 2; ++nf2) {                              \
                unsigned addr = (cb) + OFF_B + (wn + nf2*16 + l15)*ROWB + (kk + lh*8)*2; \
                ldsm4(bh[nf2][0], bh[nf2][1], bh[nf2][2], bh[nf2][3], addr); \
            }                                                                \
            _Pragma("unroll")                                                \
            for (int mf = 0; mf < 4; ++mf) {                                 \
                unsigned ah[4];                                              \
                unsigned addr = (cb) + OFF_A + (wm + mf*16 + l15)*ROWB + (kk + lh*8)*2; \
                ldsm4(ah[0], ah[1], ah[2], ah[3], addr);                     \
                _Pragma("unroll")                                            \
                for (int nf2 = 0; nf2 < 2; ++nf2) {                          \
                    _Pragma("unroll")                                        \
                    for (int u = 0; u < 2; ++u)                              \
                        mma16816(acc[mf][nf2*2 + u], ah, bh[nf2][u], bh[nf2][2 + u]); \
                }                                                            \
            }                                                                \
        }                                                                    \
    } while(0)

    // ---- prologue: fill buffer 0 ----
    {
        float4 bv[4];
        LOAD_A(smb, 0);
        asm volatile("cp.async.commit_group;");
        LDG_B(bv, 0, 0);
        STS_B(bv, sm, 0);
        LDG_B(bv, 0, 1);
        STS_B(bv, sm, 1);
        asm volatile("cp.async.wait_group 0;" ::: "memory");
        __syncthreads();
    }

    int buf = 0;
    for (int s = 0; s < S; ++s) {
        const unsigned cb = smb + buf * BUFSZ;
        const unsigned nb = smb + (buf ^ 1) * BUFSZ;
        char* nbg = sm + (buf ^ 1) * BUFSZ;
        const int k0n = (s + 1) * BK;
        const bool more = (s + 1 < S);
        float4 bv[4];

        if (more) {
            LDG_B(bv, k0n, 0);          // issue half0 LDGs (latency hidden by compute)
            LOAD_A(nb, k0n);            // A cp.async for next stage
            asm volatile("cp.async.commit_group;");
        }
        COMPUTE_HALF(cb, 0);
        if (more) {
            STS_B(bv, nbg, 0);
            LDG_B(bv, k0n, 1);          // half1 LDGs hidden by second compute half
        }
        COMPUTE_HALF(cb, 32);
        if (more) {
            STS_B(bv, nbg, 1);
            asm volatile("cp.async.wait_group 0;" ::: "memory");
        }
        __syncthreads();
        buf ^= 1;
    }

    // ---- epilogue ----
    const int gq = lane >> 2, tau = lane & 3;
    #pragma unroll
    for (int mf = 0; mf < 4; ++mf) {
        #pragma unroll
        for (int nf = 0; nf < 4; ++nf) {
            int col = n0 + wn + nf*8 + tau*2;
            int r0 = wm + mf*16 + gq;
            int r1 = r0 + 8;
            if (r0 < rows) {
                float* d = C + (size_t)(base_pos + mtile*BM + r0) * ldc + col;
                d[0] = acc[mf][nf][0]; d[1] = acc[mf][nf][1];
            }
            if (r1 < rows) {
                float* d = C + (size_t)(base_pos + mtile*BM + r1) * ldc + col;
                d[0] = acc[mf][nf][2]; d[1] = acc[mf][nf][3];
            }
        }
    }
}

// ---------------- combine ----------------
__global__ __launch_bounds__(256) void combine_kernel(float* __restrict__ out)
{
    const int t = blockIdx.x;
    const int tid = threadIdx.x;
    __shared__ float w[TOPK];
    __shared__ int   pos[TOPK];
    if (tid < TOPK) {
        w[tid]   = g_topk_w[t*TOPK + tid];
        pos[tid] = g_pair_pos[t*TOPK + tid];
    }
    __syncthreads();
    const float4* sh = (const float4*)(g_pairout + (size_t)(NROUTED + t) * HH);
    const float4* p0 = (const float4*)(g_pairout + (size_t)pos[0] * HH);
    const float4* p1 = (const float4*)(g_pairout + (size_t)pos[1] * HH);
    const float4* p2 = (const float4*)(g_pairout + (size_t)pos[2] * HH);
    const float4* p3 = (const float4*)(g_pairout + (size_t)pos[3] * HH);
    float4* o = (float4*)(out + (size_t)t * HH);
    const float w0=w[0], w1=w[1], w2=w[2], w3=w[3];
    #pragma unroll
    for (int it = 0; it < HH/4/256; ++it) {
        int i = tid + it*256;
        float4 acc = sh[i];
        float4 v0 = p0[i], v1 = p1[i], v2 = p2[i], v3 = p3[i];
        acc.x += w0*v0.x + w1*v1.x + w2*v2.x + w3*v3.x;
        acc.y += w0*v0.y + w1*v1.y + w2*v2.y + w3*v3.y;
        acc.z += w0*v0.z + w1*v1.z + w2*v2.z + w3*v3.z;
        acc.w += w0*v0.w + w1*v1.w + w2*v2.w + w3*v3.w;
        o[i] = acc;
    }
}

// ---------------- launch ----------------
extern "C" void kernel_launch(void* const* d_in, const int* in_sizes, int n_in,
                              void* d_out, int out_size)
{
    const float* x    = (const float*)d_in[0];
    const float* gw   = (const float*)d_in[1];
    const float* bias = (const float*)d_in[2];
    const float* w1   = (const float*)d_in[3];
    const float* w3   = (const float*)d_in[4];
    const float* w2   = (const float*)d_in[5];
    const float* ws1  = (const float*)d_in[6];
    const float* ws3  = (const float*)d_in[7];
    const float* ws2  = (const float*)d_in[8];
    float* out = (float*)d_out;

    cudaFuncSetAttribute(gemm_kernel, cudaFuncAttributeMaxDynamicSharedMemorySize, SMEM_DYN);

    zero_kernel<<<1, 64>>>();
    gate_kernel<<<TT/4, 256>>>(x, gw, bias);
    offsets_kernel<<<1, 32>>>();
    scatter_kernel<<<TT/256, 256>>>();
    convx_kernel<<<TT*HH/256, 256>>>(x);

    __half *xh, *ah;
    cudaGetSymbolAddress((void**)&xh, g_xh);
    cudaGetSymbolAddress((void**)&ah, g_acth);
    float *c1, *c3, *po;
    cudaGetSymbolAddress((void**)&c1, g_C1);
    cudaGetSymbolAddress((void**)&c3, g_C3);
    cudaGetSymbolAddress((void**)&po, g_pairout);

    // phase A: C1 = X@W1^T (y<8), C3 = X@W3^T (y>=8); K=HH
    gemm_kernel<<<dim3(16, 16, EE+1), NTHR, SMEM_DYN>>>(
        xh, HH, w1, ws1, w3, ws3, HH, 8, c1, c3, II, 1);
    act_kernel<<<(int)((size_t)NPAIRS*II/4/256), 256>>>();
    // phase B: pairout = act@W2^T; K=II
    gemm_kernel<<<dim3(16, 16, EE+1), NTHR, SMEM_DYN>>>(
        ah, II, w2, ws2, w2, ws2, II, 16, po, po, HH, 0);
    combine_kernel<<<TT, 256>>>(out);
}

// round 16
// speedup vs baseline: 1.4799x; 1.0316x over previous
#include <cuda_runtime.h>
#include <cuda_fp16.h>
#include <math.h>
#include <stdint.h>

#define TT 2048
#define HH 2048
#define II 1024
#define EE 32
#define TOPK 4
#define NROUTED (TT*TOPK)
#define NPAIRS  (NROUTED + TT)

// GEMM tiling: BM=128, BN=128, BK=64, 256 thr, 2 CTA/SM
#define BM 128
#define BN 128
#define BK 64
#define NTHR 256
#define ROWB 144                   // 64 fp16 = 128B + 16B pad
#define OFF_A 0
#define OFF_B 18432                // 128*144
#define BUFSZ 36864
#define SMEM_DYN (2*BUFSZ)

// ---------------- device scratch ----------------
__device__ int   g_counts[EE];
__device__ int   g_cursor[EE];
__device__ int   g_offsets[EE];
__device__ int   g_topk_idx[NROUTED];
__device__ float g_topk_w[NROUTED];
__device__ int   g_pair_token[NROUTED];
__device__ int   g_pair_pos[NROUTED];
__device__ __half g_xh[(size_t)TT*HH];
__device__ __half g_C1h[(size_t)NPAIRS*II];
__device__ __half g_C3h[(size_t)NPAIRS*II];
__device__ __half g_acth[(size_t)NPAIRS*II];
__device__ float g_pairout[(size_t)NPAIRS*HH];

// ---------------- helpers ----------------
__device__ __forceinline__ void cvt2h(unsigned &r, float hi_elem, float lo_elem) {
    asm("cvt.rn.f16x2.f32 %0, %1, %2;" : "=r"(r) : "f"(hi_elem), "f"(lo_elem));
}
__device__ __forceinline__ void ldsm4(unsigned &r0, unsigned &r1, unsigned &r2, unsigned &r3,
                                      unsigned addr) {
    asm volatile("ldmatrix.sync.aligned.m8n8.x4.shared.b16 {%0,%1,%2,%3}, [%4];"
                 : "=r"(r0), "=r"(r1), "=r"(r2), "=r"(r3) : "r"(addr));
}
__device__ __forceinline__ void mma16816(float* c, const unsigned* a, unsigned b0, unsigned b1) {
    asm volatile("mma.sync.aligned.m16n8k16.row.col.f32.f16.f16.f32 "
                 "{%0,%1,%2,%3}, {%4,%5,%6,%7}, {%8,%9}, {%0,%1,%2,%3};"
                 : "+f"(c[0]), "+f"(c[1]), "+f"(c[2]), "+f"(c[3])
                 : "r"(a[0]), "r"(a[1]), "r"(a[2]), "r"(a[3]), "r"(b0), "r"(b1));
}
__device__ __forceinline__ void cp16(unsigned dst, const void* src) {
    asm volatile("cp.async.cg.shared.global [%0], [%1], 16;" :: "r"(dst), "l"(src));
}

// ---------------- small kernels ----------------
__global__ void zero_kernel() {
    int i = threadIdx.x;
    if (i < EE) { g_counts[i] = 0; g_cursor[i] = 0; }
}
__global__ void offsets_kernel() {
    if (threadIdx.x == 0) {
        int s = 0;
        for (int e = 0; e < EE; ++e) { g_offsets[e] = s; s += g_counts[e]; }
    }
}
__global__ void scatter_kernel() {
    int t = blockIdx.x * blockDim.x + threadIdx.x;
    if (t >= TT) return;
    #pragma unroll
    for (int j = 0; j < TOPK; ++j) {
        int e = g_topk_idx[t*TOPK + j];
        int pos = g_offsets[e] + atomicAdd(&g_cursor[e], 1);
        g_pair_token[pos] = t;
        g_pair_pos[t*TOPK + j] = pos;
    }
}
// act = silu(C1)*C3, fp16 in/out, fp32 math
__global__ __launch_bounds__(256) void act_kernel() {
    size_t i4 = (size_t)blockIdx.x * 256 + threadIdx.x;   // group of 4 halves
    uint2 au = ((const uint2*)g_C1h)[i4];
    uint2 bu = ((const uint2*)g_C3h)[i4];
    float a0 = __half2float(__ushort_as_half((unsigned short)(au.x & 0xffff)));
    float a1 = __half2float(__ushort_as_half((unsigned short)(au.x >> 16)));
    float a2 = __half2float(__ushort_as_half((unsigned short)(au.y & 0xffff)));
    float a3 = __half2float(__ushort_as_half((unsigned short)(au.y >> 16)));
    float b0 = __half2float(__ushort_as_half((unsigned short)(bu.x & 0xffff)));
    float b1 = __half2float(__ushort_as_half((unsigned short)(bu.x >> 16)));
    float b2 = __half2float(__ushort_as_half((unsigned short)(bu.y & 0xffff)));
    float b3 = __half2float(__ushort_as_half((unsigned short)(bu.y >> 16)));
    float v0 = a0 / (1.f + expf(-a0)) * b0;
    float v1 = a1 / (1.f + expf(-a1)) * b1;
    float v2 = a2 / (1.f + expf(-a2)) * b2;
    float v3 = a3 / (1.f + expf(-a3)) * b3;
    unsigned h01, h23;
    cvt2h(h01, v1, v0);
    cvt2h(h23, v3, v2);
    ((uint2*)g_acth)[i4] = make_uint2(h01, h23);
}

// ---------------- gate + routing + fused convx ----------------
__global__ __launch_bounds__(256) void gate_kernel(
        const float* __restrict__ x, const float* __restrict__ gw,
        const float* __restrict__ bias)
{
    __shared__ float xs[4][HH];
    __shared__ float logits_s[4][EE];
    __shared__ float bias_s[EE];
    int tid = threadIdx.x;
    int t0  = blockIdx.x * 4;
    const float4* xg  = (const float4*)(x + (size_t)t0 * HH);
    float4*       xs4 = (float4*)&xs[0][0];
    #pragma unroll
    for (int i = 0; i < 8; ++i) xs4[tid + i*256] = xg[tid + i*256];
    if (tid < EE) bias_s[tid] = bias[tid];
    __syncthreads();

    // fused convx: fp16 copy of these 4 rows
    {
        uint2* dst = (uint2*)(g_xh + (size_t)t0 * HH);
        #pragma unroll
        for (int i = 0; i < 8; ++i) {
            float4 v = xs4[tid + i*256];
            unsigned h01, h23;
            cvt2h(h01, v.y, v.x);
            cvt2h(h23, v.w, v.z);
            dst[tid + i*256] = make_uint2(h01, h23);
        }
    }

    int warp = tid >> 5, lane = tid & 31;
    #pragma unroll
    for (int ei = 0; ei < 4; ++ei) {
        int e = warp*4 + ei;
        const float* gr = gw + (size_t)e * HH;
        float a0=0.f, a1=0.f, a2=0.f, a3=0.f;
        for (int h = lane; h < HH; h += 32) {
            float g = gr[h];
            a0 = fmaf(g, xs[0][h], a0); a1 = fmaf(g, xs[1][h], a1);
            a2 = fmaf(g, xs[2][h], a2); a3 = fmaf(g, xs[3][h], a3);
        }
        #pragma unroll
        for (int off = 16; off; off >>= 1) {
            a0 += __shfl_xor_sync(0xffffffffu, a0, off);
            a1 += __shfl_xor_sync(0xffffffffu, a1, off);
            a2 += __shfl_xor_sync(0xffffffffu, a2, off);
            a3 += __shfl_xor_sync(0xffffffffu, a3, off);
        }
        if (lane == 0) {
            logits_s[0][e] = a0; logits_s[1][e] = a1;
            logits_s[2][e] = a2; logits_s[3][e] = a3;
        }
    }
    __syncthreads();
    if (warp < 4) {
        int t = t0 + warp;
        float logit = logits_s[warp][lane];
        float s   = 1.f / (1.f + expf(-logit));
        float sfc = s + bias_s[lane];
        float m1 = sfc, m2 = -INFINITY;
        #pragma unroll
        for (int off = 4; off >= 1; off >>= 1) {
            float o1 = __shfl_xor_sync(0xffffffffu, m1, off);
            float o2 = __shfl_xor_sync(0xffffffffu, m2, off);
            float hi = fmaxf(m1, o1);
            float lo = fmaxf(fminf(m1, o1), fmaxf(m2, o2));
            m1 = hi; m2 = lo;
        }
        float gs = m1 + m2;
        float gv[4];
        gv[0] = __shfl_sync(0xffffffffu, gs, 0);
        gv[1] = __shfl_sync(0xffffffffu, gs, 8);
        gv[2] = __shfl_sync(0xffffffffu, gs, 16);
        gv[3] = __shfl_sync(0xffffffffu, gs, 24);
        int b1 = 0; float v1 = gv[0];
        #pragma unroll
        for (int gg = 1; gg < 4; ++gg) if (gv[gg] > v1) { v1 = gv[gg]; b1 = gg; }
        int b2 = -1; float v2 = -INFINITY;
        #pragma unroll
        for (int gg = 0; gg < 4; ++gg) {
            if (gg == b1) continue;
            if (gv[gg] > v2) { v2 = gv[gg]; b2 = gg; }
        }
        int mygrp = lane >> 3;
        float val = (mygrp == b1 || mygrp == b2) ? sfc : 0.0f;
        int sel_i[TOPK]; float sel_w[TOPK];
        float cur = val;
        #pragma unroll
        for (int j = 0; j < TOPK; ++j) {
            float bv = cur; int bi = lane;
            #pragma unroll
            for (int off = 16; off >= 1; off >>= 1) {
                float ov = __shfl_xor_sync(0xffffffffu, bv, off);
                int   oi = __shfl_xor_sync(0xffffffffu, bi, off);
                if (ov > bv || (ov == bv && oi < bi)) { bv = ov; bi = oi; }
            }
            sel_i[j] = bi;
            sel_w[j] = __shfl_sync(0xffffffffu, s, bi);
            if (lane == bi) cur = -INFINITY;
        }
        if (lane == 0) {
            float sum = sel_w[0] + sel_w[1] + sel_w[2] + sel_w[3];
            float scale = 2.5f / (sum + 1e-20f);
            #pragma unroll
            for (int j = 0; j < TOPK; ++j) {
                g_topk_idx[t*TOPK + j] = sel_i[j];
                g_topk_w[t*TOPK + j]   = sel_w[j] * scale;
                atomicAdd(&g_counts[sel_i[j]], 1);
            }
        }
    }
}

// ---------------- grouped fp16 GEMM: BK=64 (champion mainloop) ----------------
// outh!=0: store fp16 to Ch (phase A); else fp32 to Cf (phase B)
__global__ void __launch_bounds__(NTHR, 2) gemm_kernel(
    const __half* __restrict__ A, int lda,
    const float* __restrict__ Wra, const float* __restrict__ Wsa,
    const float* __restrict__ Wrb, const float* __restrict__ Wsb,
    int Kdim, int ybnd, float* __restrict__ Cfa, float* __restrict__ Cfb,
    __half* __restrict__ Cha, __half* __restrict__ Chb,
    int ldc, int gather, int outh)
{
    const int g     = blockIdx.z;
    const int mtile = blockIdx.x;
    const int y     = blockIdx.y;

    int m_count, base_pos;
    if (g < EE) { m_count = g_counts[g]; base_pos = g_offsets[g]; }
    else        { m_count = TT;          base_pos = NROUTED; }
    if (mtile * BM >= m_count) return;
    const int rows = min(BM, m_count - mtile * BM);

    const size_t wsz = (size_t)II * HH;
    const float* W;
    float* Cf;
    __half* Ch;
    int n0;
    if (y < ybnd) {
        W = (g < EE) ? (Wra + (size_t)g * wsz) : Wsa;
        Cf = Cfa; Ch = Cha; n0 = y * BN;
    } else {
        W = (g < EE) ? (Wrb + (size_t)g * wsz) : Wsb;
        Cf = Cfb; Ch = Chb; n0 = (y - ybnd) * BN;
    }

    extern __shared__ char sm[];
    __shared__ int s_toks[BM];
    const unsigned smb = (unsigned)__cvta_generic_to_shared(sm);

    const int tid = threadIdx.x;
    if (tid < BM) {
        int r = min(tid, rows - 1);
        int pos = base_pos + mtile*BM + r;
        s_toks[tid] = gather ? ((g < EE) ? g_pair_token[pos] : (mtile*BM + r)) : pos;
    }
    __syncthreads();

    const int S = Kdim / BK;
    const int warp = tid >> 5, lane = tid & 31;
    const int wm = (warp & 1) * 64;
    const int wn = (warp >> 1) * 32;
    const int l15 = lane & 15, lh = lane >> 4;

    float acc[4][4][4];
    #pragma unroll
    for (int i = 0; i < 4; ++i)
        #pragma unroll
        for (int j = 0; j < 4; ++j)
            #pragma unroll
            for (int q = 0; q < 4; ++q) acc[i][j][q] = 0.f;

    #define LOAD_A(dstb, k0) do {                                            \
        _Pragma("unroll")                                                    \
        for (int t = 0; t < 4; ++t) {                                        \
            int c = tid + t*NTHR;                                            \
            int row = c >> 3, ch = c & 7;                                    \
            const __half* srcp = A + (size_t)s_toks[row]*lda + (k0) + ch*8;  \
            cp16((dstb) + OFF_A + row*ROWB + ch*16, srcp);                   \
        }                                                                    \
    } while(0)
    #define LDG_B(bv, k0, h) do {                                            \
        _Pragma("unroll")                                                    \
        for (int t = 0; t < 4; ++t) {                                        \
            int c = tid + t*NTHR;                                            \
            int row = c >> 3, f4 = c & 7;                                    \
            (bv)[t] = *(const float4*)(W + (size_t)(n0+row)*Kdim + (k0) + (h)*32 + f4*4); \
        }                                                                    \
    } while(0)
    #define STS_B(bv, dstg, h) do {                                          \
        _Pragma("unroll")                                                    \
        for (int t = 0; t < 4; ++t) {                                        \
            int c = tid + t*NTHR;                                            \
            int row = c >> 3, f4 = c & 7;                                    \
            unsigned h01, h23;                                               \
            cvt2h(h01, (bv)[t].y, (bv)[t].x);                                \
            cvt2h(h23, (bv)[t].w, (bv)[t].z);                                \
            *(uint2*)((dstg) + OFF_B + row*ROWB + (h)*64 + f4*8) = make_uint2(h01, h23); \
        }                                                                    \
    } while(0)
    #define COMPUTE_HALF(cb, kk0) do {                                       \
        _Pragma("unroll")                                                    \
        for (int kk = (kk0); kk < (kk0) + 32; kk += 16) {                    \
            unsigned bh[2][4];                                               \
            _Pragma("unroll")                                                \
            for (int nf2 = 0; nf2 < 2; ++nf2) {                              \
                unsigned addr = (cb) + OFF_B + (wn + nf2*16 + l15)*ROWB + (kk + lh*8)*2; \
                ldsm4(bh[nf2][0], bh[nf2][1], bh[nf2][2], bh[nf2][3], addr); \
            }                                                                \
            _Pragma("unroll")                                                \
            for (int mf = 0; mf < 4; ++mf) {                                 \
                unsigned ah[4];                                              \
                unsigned addr = (cb) + OFF_A + (wm + mf*16 + l15)*ROWB + (kk + lh*8)*2; \
                ldsm4(ah[0], ah[1], ah[2], ah[3], addr);                     \
                _Pragma("unroll")                                            \
                for (int nf2 = 0; nf2 < 2; ++nf2) {                          \
                    _Pragma("unroll")                                        \
                    for (int u = 0; u < 2; ++u)                              \
                        mma16816(acc[mf][nf2*2 + u], ah, bh[nf2][u], bh[nf2][2 + u]); \
                }                                                            \
            }                                                                \
        }                                                                    \
    } while(0)

    // ---- prologue: fill buffer 0 ----
    {
        float4 bv[4];
        LOAD_A(smb, 0);
        asm volatile("cp.async.commit_group;");
        LDG_B(bv, 0, 0);
        STS_B(bv, sm, 0);
        LDG_B(bv, 0, 1);
        STS_B(bv, sm, 1);
        asm volatile("cp.async.wait_group 0;" ::: "memory");
        __syncthreads();
    }

    int buf = 0;
    for (int s = 0; s < S; ++s) {
        const unsigned cb = smb + buf * BUFSZ;
        const unsigned nb = smb + (buf ^ 1) * BUFSZ;
        char* nbg = sm + (buf ^ 1) * BUFSZ;
        const int k0n = (s + 1) * BK;
        const bool more = (s + 1 < S);
        float4 bv[4];

        if (more) {
            LDG_B(bv, k0n, 0);
            LOAD_A(nb, k0n);
            asm volatile("cp.async.commit_group;");
        }
        COMPUTE_HALF(cb, 0);
        if (more) {
            STS_B(bv, nbg, 0);
            LDG_B(bv, k0n, 1);
        }
        COMPUTE_HALF(cb, 32);
        if (more) {
            STS_B(bv, nbg, 1);
            asm volatile("cp.async.wait_group 0;" ::: "memory");
        }
        __syncthreads();
        buf ^= 1;
    }

    // ---- epilogue ----
    const int gq = lane >> 2, tau = lane & 3;
    #pragma unroll
    for (int mf = 0; mf < 4; ++mf) {
        #pragma unroll
        for (int nf = 0; nf < 4; ++nf) {
            int col = n0 + wn + nf*8 + tau*2;
            int r0 = wm + mf*16 + gq;
            int r1 = r0 + 8;
            if (outh) {
                if (r0 < rows) {
                    unsigned h01; cvt2h(h01, acc[mf][nf][1], acc[mf][nf][0]);
                    *(unsigned*)(Ch + (size_t)(base_pos + mtile*BM + r0) * ldc + col) = h01;
                }
                if (r1 < rows) {
                    unsigned h01; cvt2h(h01, acc[mf][nf][3], acc[mf][nf][2]);
                    *(unsigned*)(Ch + (size_t)(base_pos + mtile*BM + r1) * ldc + col) = h01;
                }
            } else {
                if (r0 < rows) {
                    float* d = Cf + (size_t)(base_pos + mtile*BM + r0) * ldc + col;
                    d[0] = acc[mf][nf][0]; d[1] = acc[mf][nf][1];
                }
                if (r1 < rows) {
                    float* d = Cf + (size_t)(base_pos + mtile*BM + r1) * ldc + col;
                    d[0] = acc[mf][nf][2]; d[1] = acc[mf][nf][3];
                }
            }
        }
    }
}

// ---------------- combine ----------------
__global__ __launch_bounds__(256) void combine_kernel(float* __restrict__ out)
{
    const int t = blockIdx.x;
    const int tid = threadIdx.x;
    __shared__ float w[TOPK];
    __shared__ int   pos[TOPK];
    if (tid < TOPK) {
        w[tid]   = g_topk_w[t*TOPK + tid];
        pos[tid] = g_pair_pos[t*TOPK + tid];
    }
    __syncthreads();
    const float4* sh = (const float4*)(g_pairout + (size_t)(NROUTED + t) * HH);
    const float4* p0 = (const float4*)(g_pairout + (size_t)pos[0] * HH);
    const float4* p1 = (const float4*)(g_pairout + (size_t)pos[1] * HH);
    const float4* p2 = (const float4*)(g_pairout + (size_t)pos[2] * HH);
    const float4* p3 = (const float4*)(g_pairout + (size_t)pos[3] * HH);
    float4* o = (float4*)(out + (size_t)t * HH);
    const float w0=w[0], w1=w[1], w2=w[2], w3=w[3];
    #pragma unroll
    for (int it = 0; it < HH/4/256; ++it) {
        int i = tid + it*256;
        float4 acc = sh[i];
        float4 v0 = p0[i], v1 = p1[i], v2 = p2[i], v3 = p3[i];
        acc.x += w0*v0.x + w1*v1.x + w2*v2.x + w3*v3.x;
        acc.y += w0*v0.y + w1*v1.y + w2*v2.y + w3*v3.y;
        acc.z += w0*v0.z + w1*v1.z + w2*v2.z + w3*v3.z;
        acc.w += w0*v0.w + w1*v1.w + w2*v2.w + w3*v3.w;
        o[i] = acc;
    }
}

// ---------------- launch ----------------
extern "C" void kernel_launch(void* const* d_in, const int* in_sizes, int n_in,
                              void* d_out, int out_size)
{
    const float* x    = (const float*)d_in[0];
    const float* gw   = (const float*)d_in[1];
    const float* bias = (const float*)d_in[2];
    const float* w1   = (const float*)d_in[3];
    const float* w3   = (const float*)d_in[4];
    const float* w2   = (const float*)d_in[5];
    const float* ws1  = (const float*)d_in[6];
    const float* ws3  = (const float*)d_in[7];
    const float* ws2  = (const float*)d_in[8];
    float* out = (float*)d_out;

    cudaFuncSetAttribute(gemm_kernel, cudaFuncAttributeMaxDynamicSharedMemorySize, SMEM_DYN);

    zero_kernel<<<1, 64>>>();
    gate_kernel<<<TT/4, 256>>>(x, gw, bias);
    offsets_kernel<<<1, 32>>>();
    scatter_kernel<<<TT/256, 256>>>();

    __half *xh, *ah, *c1h, *c3h;
    cudaGetSymbolAddress((void**)&xh, g_xh);
    cudaGetSymbolAddress((void**)&ah, g_acth);
    cudaGetSymbolAddress((void**)&c1h, g_C1h);
    cudaGetSymbolAddress((void**)&c3h, g_C3h);
    float* po;
    cudaGetSymbolAddress((void**)&po, g_pairout);

    // phase A: C1h = X@W1^T (y<8), C3h = X@W3^T (y>=8); fp16 out
    gemm_kernel<<<dim3(16, 16, EE+1), NTHR, SMEM_DYN>>>(
        xh, HH, w1, ws1, w3, ws3, HH, 8, nullptr, nullptr, c1h, c3h, II, 1, 1);
    act_kernel<<<(int)((size_t)NPAIRS*II/4/256), 256>>>();
    // phase B: pairout = act@W2^T; fp32 out
    gemm_kernel<<<dim3(16, 16, EE+1), NTHR, SMEM_DYN>>>(
        ah, II, w2, ws2, w2, ws2, II, 16, po, po, nullptr, nullptr, HH, 0, 0);
    combine_kernel<<<TT, 256>>>(out);
}

// round 17
// speedup vs baseline: 1.5260x; 1.0311x over previous
#include <cuda_runtime.h>
#include <cuda_fp16.h>
#include <math.h>
#include <stdint.h>

#define TT 2048
#define HH 2048
#define II 1024
#define EE 32
#define TOPK 4
#define NROUTED (TT*TOPK)
#define NPAIRS  (NROUTED + TT)

// GEMM tiling: BM=128, BN=128, BK=64, 256 thr, 2 CTA/SM
#define BM 128
#define BN 128
#define BK 64
#define NTHR 256
#define ROWB 144                   // 64 fp16 = 128B + 16B pad
#define OFF_A 0
#define OFF_B 18432                // 128*144
#define BUFSZ 36864
#define SMEM_DYN (2*BUFSZ)

// ---------------- device scratch ----------------
__device__ int   g_counts[EE];
__device__ int   g_cursor[EE];
__device__ int   g_offsets[EE];
__device__ int   g_topk_idx[NROUTED];
__device__ float g_topk_w[NROUTED];
__device__ int   g_pair_token[NROUTED];
__device__ int   g_pair_pos[NROUTED];
__device__ __half g_xh[(size_t)TT*HH];
__device__ __half g_C1h[(size_t)NPAIRS*II];
__device__ __half g_C3h[(size_t)NPAIRS*II];
__device__ __half g_acth[(size_t)NPAIRS*II];
__device__ __half g_pairouth[(size_t)NPAIRS*HH];

// ---------------- helpers ----------------
__device__ __forceinline__ void cvt2h(unsigned &r, float hi_elem, float lo_elem) {
    asm("cvt.rn.f16x2.f32 %0, %1, %2;" : "=r"(r) : "f"(hi_elem), "f"(lo_elem));
}
__device__ __forceinline__ void ldsm4(unsigned &r0, unsigned &r1, unsigned &r2, unsigned &r3,
                                      unsigned addr) {
    asm volatile("ldmatrix.sync.aligned.m8n8.x4.shared.b16 {%0,%1,%2,%3}, [%4];"
                 : "=r"(r0), "=r"(r1), "=r"(r2), "=r"(r3) : "r"(addr));
}
__device__ __forceinline__ void mma16816(float* c, const unsigned* a, unsigned b0, unsigned b1) {
    asm volatile("mma.sync.aligned.m16n8k16.row.col.f32.f16.f16.f32 "
                 "{%0,%1,%2,%3}, {%4,%5,%6,%7}, {%8,%9}, {%0,%1,%2,%3};"
                 : "+f"(c[0]), "+f"(c[1]), "+f"(c[2]), "+f"(c[3])
                 : "r"(a[0]), "r"(a[1]), "r"(a[2]), "r"(a[3]), "r"(b0), "r"(b1));
}
__device__ __forceinline__ void cp16(unsigned dst, const void* src) {
    asm volatile("cp.async.cg.shared.global [%0], [%1], 16;" :: "r"(dst), "l"(src));
}

// ---------------- small kernels ----------------
__global__ void zero_kernel() {
    int i = threadIdx.x;
    if (i < EE) { g_counts[i] = 0; g_cursor[i] = 0; }
}
__global__ void offsets_kernel() {
    if (threadIdx.x == 0) {
        int s = 0;
        for (int e = 0; e < EE; ++e) { g_offsets[e] = s; s += g_counts[e]; }
    }
}
__global__ void scatter_kernel() {
    int t = blockIdx.x * blockDim.x + threadIdx.x;
    if (t >= TT) return;
    #pragma unroll
    for (int j = 0; j < TOPK; ++j) {
        int e = g_topk_idx[t*TOPK + j];
        int pos = g_offsets[e] + atomicAdd(&g_cursor[e], 1);
        g_pair_token[pos] = t;
        g_pair_pos[t*TOPK + j] = pos;
    }
}
// act = silu(C1)*C3, fp16 in/out, fp32 math
__global__ __launch_bounds__(256) void act_kernel() {
    size_t i4 = (size_t)blockIdx.x * 256 + threadIdx.x;
    uint2 au = ((const uint2*)g_C1h)[i4];
    uint2 bu = ((const uint2*)g_C3h)[i4];
    float a0 = __half2float(__ushort_as_half((unsigned short)(au.x & 0xffff)));
    float a1 = __half2float(__ushort_as_half((unsigned short)(au.x >> 16)));
    float a2 = __half2float(__ushort_as_half((unsigned short)(au.y & 0xffff)));
    float a3 = __half2float(__ushort_as_half((unsigned short)(au.y >> 16)));
    float b0 = __half2float(__ushort_as_half((unsigned short)(bu.x & 0xffff)));
    float b1 = __half2float(__ushort_as_half((unsigned short)(bu.x >> 16)));
    float b2 = __half2float(__ushort_as_half((unsigned short)(bu.y & 0xffff)));
    float b3 = __half2float(__ushort_as_half((unsigned short)(bu.y >> 16)));
    float v0 = a0 / (1.f + expf(-a0)) * b0;
    float v1 = a1 / (1.f + expf(-a1)) * b1;
    float v2 = a2 / (1.f + expf(-a2)) * b2;
    float v3 = a3 / (1.f + expf(-a3)) * b3;
    unsigned h01, h23;
    cvt2h(h01, v1, v0);
    cvt2h(h23, v3, v2);
    ((uint2*)g_acth)[i4] = make_uint2(h01, h23);
}

// ---------------- gate + routing + fused convx ----------------
__global__ __launch_bounds__(256) void gate_kernel(
        const float* __restrict__ x, const float* __restrict__ gw,
        const float* __restrict__ bias)
{
    __shared__ float xs[4][HH];
    __shared__ float logits_s[4][EE];
    __shared__ float bias_s[EE];
    int tid = threadIdx.x;
    int t0  = blockIdx.x * 4;
    const float4* xg  = (const float4*)(x + (size_t)t0 * HH);
    float4*       xs4 = (float4*)&xs[0][0];
    #pragma unroll
    for (int i = 0; i < 8; ++i) xs4[tid + i*256] = xg[tid + i*256];
    if (tid < EE) bias_s[tid] = bias[tid];
    __syncthreads();

    // fused convx: fp16 copy of these 4 rows
    {
        uint2* dst = (uint2*)(g_xh + (size_t)t0 * HH);
        #pragma unroll
        for (int i = 0; i < 8; ++i) {
            float4 v = xs4[tid + i*256];
            unsigned h01, h23;
            cvt2h(h01, v.y, v.x);
            cvt2h(h23, v.w, v.z);
            dst[tid + i*256] = make_uint2(h01, h23);
        }
    }

    int warp = tid >> 5, lane = tid & 31;
    #pragma unroll
    for (int ei = 0; ei < 4; ++ei) {
        int e = warp*4 + ei;
        const float* gr = gw + (size_t)e * HH;
        float a0=0.f, a1=0.f, a2=0.f, a3=0.f;
        for (int h = lane; h < HH; h += 32) {
            float g = gr[h];
            a0 = fmaf(g, xs[0][h], a0); a1 = fmaf(g, xs[1][h], a1);
            a2 = fmaf(g, xs[2][h], a2); a3 = fmaf(g, xs[3][h], a3);
        }
        #pragma unroll
        for (int off = 16; off; off >>= 1) {
            a0 += __shfl_xor_sync(0xffffffffu, a0, off);
            a1 += __shfl_xor_sync(0xffffffffu, a1, off);
            a2 += __shfl_xor_sync(0xffffffffu, a2, off);
            a3 += __shfl_xor_sync(0xffffffffu, a3, off);
        }
        if (lane == 0) {
            logits_s[0][e] = a0; logits_s[1][e] = a1;
            logits_s[2][e] = a2; logits_s[3][e] = a3;
        }
    }
    __syncthreads();
    if (warp < 4) {
        int t = t0 + warp;
        float logit = logits_s[warp][lane];
        float s   = 1.f / (1.f + expf(-logit));
        float sfc = s + bias_s[lane];
        float m1 = sfc, m2 = -INFINITY;
        #pragma unroll
        for (int off = 4; off >= 1; off >>= 1) {
            float o1 = __shfl_xor_sync(0xffffffffu, m1, off);
            float o2 = __shfl_xor_sync(0xffffffffu, m2, off);
            float hi = fmaxf(m1, o1);
            float lo = fmaxf(fminf(m1, o1), fmaxf(m2, o2));
            m1 = hi; m2 = lo;
        }
        float gs = m1 + m2;
        float gv[4];
        gv[0] = __shfl_sync(0xffffffffu, gs, 0);
        gv[1] = __shfl_sync(0xffffffffu, gs, 8);
        gv[2] = __shfl_sync(0xffffffffu, gs, 16);
        gv[3] = __shfl_sync(0xffffffffu, gs, 24);
        int b1 = 0; float v1 = gv[0];
        #pragma unroll
        for (int gg = 1; gg < 4; ++gg) if (gv[gg] > v1) { v1 = gv[gg]; b1 = gg; }
        int b2 = -1; float v2 = -INFINITY;
        #pragma unroll
        for (int gg = 0; gg < 4; ++gg) {
            if (gg == b1) continue;
            if (gv[gg] > v2) { v2 = gv[gg]; b2 = gg; }
        }
        int mygrp = lane >> 3;
        float val = (mygrp == b1 || mygrp == b2) ? sfc : 0.0f;
        int sel_i[TOPK]; float sel_w[TOPK];
        float cur = val;
        #pragma unroll
        for (int j = 0; j < TOPK; ++j) {
            float bv = cur; int bi = lane;
            #pragma unroll
            for (int off = 16; off >= 1; off >>= 1) {
                float ov = __shfl_xor_sync(0xffffffffu, bv, off);
                int   oi = __shfl_xor_sync(0xffffffffu, bi, off);
                if (ov > bv || (ov == bv && oi < bi)) { bv = ov; bi = oi; }
            }
            sel_i[j] = bi;
            sel_w[j] = __shfl_sync(0xffffffffu, s, bi);
            if (lane == bi) cur = -INFINITY;
        }
        if (lane == 0) {
            float sum = sel_w[0] + sel_w[1] + sel_w[2] + sel_w[3];
            float scale = 2.5f / (sum + 1e-20f);
            #pragma unroll
            for (int j = 0; j < TOPK; ++j) {
                g_topk_idx[t*TOPK + j] = sel_i[j];
                g_topk_w[t*TOPK + j]   = sel_w[j] * scale;
                atomicAdd(&g_counts[sel_i[j]], 1);
            }
        }
    }
}

// ---------------- grouped fp16 GEMM: BK=64 (champion mainloop) ----------------
// stores fp16 to Ch{a,b}
__global__ void __launch_bounds__(NTHR, 2) gemm_kernel(
    const __half* __restrict__ A, int lda,
    const float* __restrict__ Wra, const float* __restrict__ Wsa,
    const float* __restrict__ Wrb, const float* __restrict__ Wsb,
    int Kdim, int ybnd, __half* __restrict__ Cha, __half* __restrict__ Chb,
    int ldc, int gather)
{
    const int g     = blockIdx.z;
    const int mtile = blockIdx.x;
    const int y     = blockIdx.y;

    int m_count, base_pos;
    if (g < EE) { m_count = g_counts[g]; base_pos = g_offsets[g]; }
    else        { m_count = TT;          base_pos = NROUTED; }
    if (mtile * BM >= m_count) return;
    const int rows = min(BM, m_count - mtile * BM);

    const size_t wsz = (size_t)II * HH;
    const float* W;
    __half* Ch;
    int n0;
    if (y < ybnd) {
        W = (g < EE) ? (Wra + (size_t)g * wsz) : Wsa;
        Ch = Cha; n0 = y * BN;
    } else {
        W = (g < EE) ? (Wrb + (size_t)g * wsz) : Wsb;
        Ch = Chb; n0 = (y - ybnd) * BN;
    }

    extern __shared__ char sm[];
    __shared__ int s_toks[BM];
    const unsigned smb = (unsigned)__cvta_generic_to_shared(sm);

    const int tid = threadIdx.x;
    if (tid < BM) {
        int r = min(tid, rows - 1);
        int pos = base_pos + mtile*BM + r;
        s_toks[tid] = gather ? ((g < EE) ? g_pair_token[pos] : (mtile*BM + r)) : pos;
    }
    __syncthreads();

    const int S = Kdim / BK;
    const int warp = tid >> 5, lane = tid & 31;
    const int wm = (warp & 1) * 64;
    const int wn = (warp >> 1) * 32;
    const int l15 = lane & 15, lh = lane >> 4;

    float acc[4][4][4];
    #pragma unroll
    for (int i = 0; i < 4; ++i)
        #pragma unroll
        for (int j = 0; j < 4; ++j)
            #pragma unroll
            for (int q = 0; q < 4; ++q) acc[i][j][q] = 0.f;

    #define LOAD_A(dstb, k0) do {                                            \
        _Pragma("unroll")                                                    \
        for (int t = 0; t < 4; ++t) {                                        \
            int c = tid + t*NTHR;                                            \
            int row = c >> 3, ch = c & 7;                                    \
            const __half* srcp = A + (size_t)s_toks[row]*lda + (k0) + ch*8;  \
            cp16((dstb) + OFF_A + row*ROWB + ch*16, srcp);                   \
        }                                                                    \
    } while(0)
    #define LDG_B(bv, k0, h) do {                                            \
        _Pragma("unroll")                                                    \
        for (int t = 0; t < 4; ++t) {                                        \
            int c = tid + t*NTHR;                                            \
            int row = c >> 3, f4 = c & 7;                                    \
            (bv)[t] = *(const float4*)(W + (size_t)(n0+row)*Kdim + (k0) + (h)*32 + f4*4); \
        }                                                                    \
    } while(0)
    #define STS_B(bv, dstg, h) do {                                          \
        _Pragma("unroll")                                                    \
        for (int t = 0; t < 4; ++t) {                                        \
            int c = tid + t*NTHR;                                            \
            int row = c >> 3, f4 = c & 7;                                    \
            unsigned h01, h23;                                               \
            cvt2h(h01, (bv)[t].y, (bv)[t].x);                                \
            cvt2h(h23, (bv)[t].w, (bv)[t].z);                                \
            *(uint2*)((dstg) + OFF_B + row*ROWB + (h)*64 + f4*8) = make_uint2(h01, h23); \
        }                                                                    \
    } while(0)
    #define COMPUTE_HALF(cb, kk0) do {                                       \
        _Pragma("unroll")                                                    \
        for (int kk = (kk0); kk < (kk0) + 32; kk += 16) {                    \
            unsigned bh[2][4];                                               \
            _Pragma("unroll")                                                \
            for (int nf2 = 0; nf2 < 2; ++nf2) {                              \
                unsigned addr = (cb) + OFF_B + (wn + nf2*16 + l15)*ROWB + (kk + lh*8)*2; \
                ldsm4(bh[nf2][0], bh[nf2][1], bh[nf2][2], bh[nf2][3], addr); \
            }                                                                \
            _Pragma("unroll")                                                \
            for (int mf = 0; mf < 4; ++mf) {                                 \
                unsigned ah[4];                                              \
                unsigned addr = (cb) + OFF_A + (wm + mf*16 + l15)*ROWB + (kk + lh*8)*2; \
                ldsm4(ah[0], ah[1], ah[2], ah[3], addr);                     \
                _Pragma("unroll")                                            \
                for (int nf2 = 0; nf2 < 2; ++nf2) {                          \
                    _Pragma("unroll")                                        \
                    for (int u = 0; u < 2; ++u)                              \
                        mma16816(acc[mf][nf2*2 + u], ah, bh[nf2][u], bh[nf2][2 + u]); \
                }                                                            \
            }                                                                \
        }                                                                    \
    } while(0)

    // ---- prologue: fill buffer 0 ----
    {
        float4 bv[4];
        LOAD_A(smb, 0);
        asm volatile("cp.async.commit_group;");
        LDG_B(bv, 0, 0);
        STS_B(bv, sm, 0);
        LDG_B(bv, 0, 1);
        STS_B(bv, sm, 1);
        asm volatile("cp.async.wait_group 0;" ::: "memory");
        __syncthreads();
    }

    int buf = 0;
    for (int s = 0; s < S; ++s) {
        const unsigned cb = smb + buf * BUFSZ;
        const unsigned nb = smb + (buf ^ 1) * BUFSZ;
        char* nbg = sm + (buf ^ 1) * BUFSZ;
        const int k0n = (s + 1) * BK;
        const bool more = (s + 1 < S);
        float4 bv[4];

        if (more) {
            LDG_B(bv, k0n, 0);
            LOAD_A(nb, k0n);
            asm volatile("cp.async.commit_group;");
        }
        COMPUTE_HALF(cb, 0);
        if (more) {
            STS_B(bv, nbg, 0);
            LDG_B(bv, k0n, 1);
        }
        COMPUTE_HALF(cb, 32);
        if (more) {
            STS_B(bv, nbg, 1);
            asm volatile("cp.async.wait_group 0;" ::: "memory");
        }
        __syncthreads();
        buf ^= 1;
    }

    // ---- epilogue: fp16 stores ----
    const int gq = lane >> 2, tau = lane & 3;
    #pragma unroll
    for (int mf = 0; mf < 4; ++mf) {
        #pragma unroll
        for (int nf = 0; nf < 4; ++nf) {
            int col = n0 + wn + nf*8 + tau*2;
            int r0 = wm + mf*16 + gq;
            int r1 = r0 + 8;
            if (r0 < rows) {
                unsigned h01; cvt2h(h01, acc[mf][nf][1], acc[mf][nf][0]);
                *(unsigned*)(Ch + (size_t)(base_pos + mtile*BM + r0) * ldc + col) = h01;
            }
            if (r1 < rows) {
                unsigned h01; cvt2h(h01, acc[mf][nf][3], acc[mf][nf][2]);
                *(unsigned*)(Ch + (size_t)(base_pos + mtile*BM + r1) * ldc + col) = h01;
            }
        }
    }
}

// ---------------- combine: fp16 pairout in, fp32 out ----------------
__global__ __launch_bounds__(256) void combine_kernel(float* __restrict__ out)
{
    const int t = blockIdx.x;
    const int tid = threadIdx.x;
    __shared__ float w[TOPK];
    __shared__ int   pos[TOPK];
    if (tid < TOPK) {
        w[tid]   = g_topk_w[t*TOPK + tid];
        pos[tid] = g_pair_pos[t*TOPK + tid];
    }
    __syncthreads();
    const __half2* sh = (const __half2*)(g_pairouth + (size_t)(NROUTED + t) * HH);
    const __half2* p0 = (const __half2*)(g_pairouth + (size_t)pos[0] * HH);
    const __half2* p1 = (const __half2*)(g_pairouth + (size_t)pos[1] * HH);
    const __half2* p2 = (const __half2*)(g_pairouth + (size_t)pos[2] * HH);
    const __half2* p3 = (const __half2*)(g_pairouth + (size_t)pos[3] * HH);
    float2* o = (float2*)(out + (size_t)t * HH);
    const float w0=w[0], w1=w[1], w2=w[2], w3=w[3];
    #pragma unroll
    for (int it = 0; it < HH/2/256; ++it) {
        int i = tid + it*256;
        float2 acc = __half22float2(sh[i]);
        float2 v0 = __half22float2(p0[i]);
        float2 v1 = __half22float2(p1[i]);
        float2 v2 = __half22float2(p2[i]);
        float2 v3 = __half22float2(p3[i]);
        acc.x += w0*v0.x + w1*v1.x + w2*v2.x + w3*v3.x;
        acc.y += w0*v0.y + w1*v1.y + w2*v2.y + w3*v3.y;
        o[i] = acc;
    }
}

// ---------------- launch ----------------
extern "C" void kernel_launch(void* const* d_in, const int* in_sizes, int n_in,
                              void* d_out, int out_size)
{
    const float* x    = (const float*)d_in[0];
    const float* gw   = (const float*)d_in[1];
    const float* bias = (const float*)d_in[2];
    const float* w1   = (const float*)d_in[3];
    const float* w3   = (const float*)d_in[4];
    const float* w2   = (const float*)d_in[5];
    const float* ws1  = (const float*)d_in[6];
    const float* ws3  = (const float*)d_in[7];
    const float* ws2  = (const float*)d_in[8];
    float* out = (float*)d_out;

    cudaFuncSetAttribute(gemm_kernel, cudaFuncAttributeMaxDynamicSharedMemorySize, SMEM_DYN);

    zero_kernel<<<1, 64>>>();
    gate_kernel<<<TT/4, 256>>>(x, gw, bias);
    offsets_kernel<<<1, 32>>>();
    scatter_kernel<<<TT/256, 256>>>();

    __half *xh, *ah, *c1h, *c3h, *poh;
    cudaGetSymbolAddress((void**)&xh, g_xh);
    cudaGetSymbolAddress((void**)&ah, g_acth);
    cudaGetSymbolAddress((void**)&c1h, g_C1h);
    cudaGetSymbolAddress((void**)&c3h, g_C3h);
    cudaGetSymbolAddress((void**)&poh, g_pairouth);

    // phase A: C1h = X@W1^T (y<8), C3h = X@W3^T (y>=8); fp16 out
    gemm_kernel<<<dim3(16, 16, EE+1), NTHR, SMEM_DYN>>>(
        xh, HH, w1, ws1, w3, ws3, HH, 8, c1h, c3h, II, 1);
    act_kernel<<<(int)((size_t)NPAIRS*II/4/256), 256>>>();
    // phase B: pairouth = act@W2^T; fp16 out
    gemm_kernel<<<dim3(16, 16, EE+1), NTHR, SMEM_DYN>>>(
        ah, II, w2, ws2, w2, ws2, II, 16, poh, poh, HH, 0);
    combine_kernel<<<TT, 256>>>(out);
}